// round 12
// baseline (speedup 1.0000x reference)
#include <cuda_runtime.h>
#include <cuda_fp16.h>
#include <math.h>
#include <stdint.h>

// ---------------- problem constants ----------------
#define NB    64
#define LW    128
#define DM    384
#define HH    8
#define DFF   1536
#define NWIN  (NB*LW)     // 8192
#define FEATD 2048

// ---------------- scratch (device globals, alloc-free) ----------------
__device__ __half h_feat[NWIN*FEATD];
__device__ __half h_t  [NWIN*DM];
__device__ __half h_q  [NWIN*DM];
__device__ __half h_k  [NWIN*DM];
__device__ __half h_v  [NWIN*DM];
__device__ __half h_ao [NWIN*DM];
__device__ __half h_buf[NWIN*DM];
__device__ __half h_mid[NWIN*DFF];
__device__ float  d_pe [LW*DM];
__device__ __half h_bte[DM*FEATD];
__device__ __half h_btq[4][DM*DM];
__device__ __half h_btk[4][DM*DM];
__device__ __half h_btv[4][DM*DM];
__device__ __half h_bto[4][DM*DM];
__device__ __half h_bt1[4][DFF*DM];
__device__ __half h_bt2[4][DM*DFF];

// ---------------- helpers ----------------
__device__ __forceinline__ uint32_t smem_u32(const void* p) {
    uint32_t a;
    asm("{ .reg .u64 t; cvta.to.shared.u64 t, %1; cvt.u32.u64 %0, t; }" : "=r"(a) : "l"(p));
    return a;
}
__device__ __forceinline__ void cp16(uint32_t s, const void* g) {
    asm volatile("cp.async.cg.shared.global [%0], [%1], 16;" :: "r"(s), "l"(g));
}
__device__ __forceinline__ void cp_commit() { asm volatile("cp.async.commit_group;"); }
template<int N> __device__ __forceinline__ void cp_wait() {
    asm volatile("cp.async.wait_group %0;" :: "n"(N));
}
__device__ __forceinline__ void ldsm4(uint32_t* r, uint32_t addr) {
    asm volatile("ldmatrix.sync.aligned.m8n8.x4.shared.b16 {%0,%1,%2,%3}, [%4];"
        : "=r"(r[0]), "=r"(r[1]), "=r"(r[2]), "=r"(r[3]) : "r"(addr));
}
__device__ __forceinline__ void ldsm4t(uint32_t* r, uint32_t addr) {
    asm volatile("ldmatrix.sync.aligned.m8n8.x4.trans.shared.b16 {%0,%1,%2,%3}, [%4];"
        : "=r"(r[0]), "=r"(r[1]), "=r"(r[2]), "=r"(r[3]) : "r"(addr));
}
// m16n8k16 fp16 mma, fp32 accumulate
__device__ __forceinline__ void mma16(float* c, const uint32_t* a, uint32_t b0, uint32_t b1) {
    asm volatile("mma.sync.aligned.m16n8k16.row.col.f32.f16.f16.f32 "
        "{%0,%1,%2,%3}, {%4,%5,%6,%7}, {%8,%9}, {%0,%1,%2,%3};"
        : "+f"(c[0]), "+f"(c[1]), "+f"(c[2]), "+f"(c[3])
        : "r"(a[0]), "r"(a[1]), "r"(a[2]), "r"(a[3]), "r"(b0), "r"(b1));
}

// SMEM per stage: A [64][40] halfs + B [128][40] halfs (rows 32 -> pad 40 halfs = 80 B)
#define ROWB    80
#define ATILEB  (64*ROWB)       // 5120
#define BTILEB  (128*ROWB)      // 10240
#define STAGEB  (ATILEB+BTILEB) // 15360
#define GSMEM   (3*STAGEB)      // 46080 (3-stage)

// ---------------- fp16 mma GEMM core: C tile 64x128, K chunks of 32, 3-stage pipeline ----------------
// epi: 0=+bias ; 1=relu(+bias) ; 2=+bias+extra_half[m*ldc+c] ; 3=relu(+bias)+pe_f32[(m&127)*ldc+c]
__device__ __forceinline__ void gemm_core(
    const __half* __restrict__ A, const __half* __restrict__ BtBlk,
    const float* __restrict__ bias, const void* __restrict__ extra,
    __half* __restrict__ C, int K, int ldc, int epi, int row0, int col0)
{
    extern __shared__ float sm[];
    uint32_t sbase = smem_u32(sm);
    int tid = threadIdx.x;

    int lrow = tid >> 2, lc = tid & 3;
    const __half* Ag  = A + (size_t)(row0 + lrow) * K + lc * 8;
    const __half* Bg0 = BtBlk + (size_t)lrow * K + lc * 8;
    const __half* Bg1 = BtBlk + (size_t)(lrow + 64) * K + lc * 8;
    uint32_t sA  = sbase + lrow * ROWB + lc * 16;
    uint32_t sB0 = sbase + ATILEB + lrow * ROWB + lc * 16;
    uint32_t sB1 = sB0 + 64 * ROWB;
    int nk = K >> 5;

    // prologue: chunks 0,1 -> slots 0,1  (all our K have nk >= 12)
    cp16(sA, Ag); cp16(sB0, Bg0); cp16(sB1, Bg1); cp_commit();
    cp16(sA + STAGEB, Ag + 32); cp16(sB0 + STAGEB, Bg0 + 32); cp16(sB1 + STAGEB, Bg1 + 32); cp_commit();

    int lane = tid & 31, w = tid >> 5, wm = w & 1, wn = w >> 1;
    uint32_t aoff = sbase + (wm * 32 + (lane & 15)) * ROWB + (lane >> 4) * 16;
    uint32_t boff = sbase + ATILEB + (wn * 32 + (lane & 15)) * ROWB + (lane >> 4) * 16;

    float c[2][4][4];
    #pragma unroll
    for (int i = 0; i < 2; i++)
        #pragma unroll
        for (int j = 0; j < 4; j++)
            #pragma unroll
            for (int q = 0; q < 4; q++) c[i][j][q] = 0.f;

    for (int kc = 0; kc < nk; kc++) {
        if (kc == nk - 1) cp_wait<0>(); else cp_wait<1>();
        __syncthreads();
        if (kc + 2 < nk) {
            uint32_t off = ((kc + 2) % 3) * STAGEB;
            int ho = (kc + 2) * 32;
            cp16(sA + off,  Ag + ho);
            cp16(sB0 + off, Bg0 + ho);
            cp16(sB1 + off, Bg1 + ho);
            cp_commit();
        }
        uint32_t st = (kc % 3) * STAGEB;
        uint32_t ab = aoff + st;
        uint32_t bb = boff + st;
        #pragma unroll
        for (int ks = 0; ks < 2; ks++) {
            uint32_t af[2][4], bf[2][4];
            #pragma unroll
            for (int mf = 0; mf < 2; mf++)
                ldsm4(af[mf], ab + mf * 16 * ROWB + ks * 32);
            #pragma unroll
            for (int np = 0; np < 2; np++)
                ldsm4(bf[np], bb + np * 16 * ROWB + ks * 32);
            #pragma unroll
            for (int mf = 0; mf < 2; mf++)
                #pragma unroll
                for (int nf = 0; nf < 4; nf++) {
                    int np = nf >> 1, sub = nf & 1;
                    mma16(c[mf][nf], af[mf], bf[np][sub], bf[np][sub + 2]);
                }
        }
    }

    // epilogue -> half
    #pragma unroll
    for (int mf = 0; mf < 2; mf++) {
        #pragma unroll
        for (int half = 0; half < 2; half++) {
            int r = row0 + wm * 32 + mf * 16 + (lane >> 2) + half * 8;
            #pragma unroll
            for (int nf = 0; nf < 4; nf++) {
                int col = col0 + wn * 32 + nf * 8 + (lane & 3) * 2;
                float v0 = c[mf][nf][half * 2 + 0] + bias[col];
                float v1 = c[mf][nf][half * 2 + 1] + bias[col + 1];
                if (epi == 1) { v0 = fmaxf(v0, 0.f); v1 = fmaxf(v1, 0.f); }
                else if (epi == 2) {
                    __half2 e = *(const __half2*)((const __half*)extra + (size_t)r * ldc + col);
                    v0 += __low2float(e); v1 += __high2float(e);
                } else if (epi == 3) {
                    const float* ex = (const float*)extra + (size_t)(r & (LW - 1)) * ldc;
                    v0 = fmaxf(v0, 0.f) + ex[col];
                    v1 = fmaxf(v1, 0.f) + ex[col + 1];
                }
                *(__half2*)(C + (size_t)r * ldc + col) = __floats2half2_rn(v0, v1);
            }
        }
    }
}

__global__ __launch_bounds__(256, 3) void gemm_h(
    const __half* __restrict__ A, const __half* __restrict__ Bt,
    const float* __restrict__ bias, const void* __restrict__ extra,
    __half* __restrict__ C, int K, int N, int epi)
{
    gemm_core(A, Bt + (size_t)blockIdx.x * 128 * K, bias, extra, C, K, N, epi,
              blockIdx.y * 64, blockIdx.x * 128);
}

__global__ __launch_bounds__(256, 3) void gemm_h_qkv(
    const __half* __restrict__ A,
    const __half* __restrict__ btq, const __half* __restrict__ btk, const __half* __restrict__ btv,
    const float* __restrict__ bqv, const float* __restrict__ bkv, const float* __restrict__ bvv,
    __half* __restrict__ q, __half* __restrict__ k, __half* __restrict__ v)
{
    int sel = blockIdx.x / 3, j = blockIdx.x % 3;
    const __half* Bt   = sel == 0 ? btq : (sel == 1 ? btk : btv);
    const float* bias  = sel == 0 ? bqv : (sel == 1 ? bkv : bvv);
    __half*      C     = sel == 0 ? q   : (sel == 1 ? k   : v);
    gemm_core(A, Bt + (size_t)j * 128 * DM, bias, nullptr, C, DM, DM, 0,
              blockIdx.y * 64, j * 128);
}

// ---------------- batched weight transpose -> fp16 ----------------
__global__ void transpose_h(const float* __restrict__ in, __half* __restrict__ out, int Kd, int Nd)
{
    size_t mstride = (size_t)Kd * Nd;
    in  += blockIdx.z * mstride;
    out += blockIdx.z * mstride;
    __shared__ float tile[32][33];
    int kb = blockIdx.x * 32, nb = blockIdx.y * 32;
    int tx = threadIdx.x, ty = threadIdx.y;
    #pragma unroll
    for (int j = 0; j < 32; j += 8)
        tile[ty + j][tx] = in[(size_t)(kb + ty + j) * Nd + nb + tx];
    __syncthreads();
    #pragma unroll
    for (int j = 0; j < 32; j += 8)
        out[(size_t)(nb + ty + j) * Kd + kb + tx] = __float2half_rn(tile[tx][ty + j]);
}

__global__ void transpose_h_qkvo(
    const float* __restrict__ Wq, const float* __restrict__ Wk,
    const float* __restrict__ Wv, const float* __restrict__ Wo,
    __half* __restrict__ oq, __half* __restrict__ ok,
    __half* __restrict__ ov, __half* __restrict__ oo)
{
    int z = blockIdx.z, sel = z >> 2, layer = z & 3;
    const float* in = (sel == 0 ? Wq : sel == 1 ? Wk : sel == 2 ? Wv : Wo)
                      + (size_t)layer * DM * DM;
    __half* out = (sel == 0 ? oq : sel == 1 ? ok : sel == 2 ? ov : oo)
                  + (size_t)layer * DM * DM;
    __shared__ float tile[32][33];
    int kb = blockIdx.x * 32, nb = blockIdx.y * 32;
    int tx = threadIdx.x, ty = threadIdx.y;
    #pragma unroll
    for (int j = 0; j < 32; j += 8)
        tile[ty + j][tx] = in[(size_t)(kb + ty + j) * DM + nb + tx];
    __syncthreads();
    #pragma unroll
    for (int j = 0; j < 32; j += 8)
        out[(size_t)(nb + ty + j) * DM + kb + tx] = __float2half_rn(tile[tx][ty + j]);
}

// ---------------- positional encoding ----------------
__global__ void pe_kernel() {
    int idx = blockIdx.x * blockDim.x + threadIdx.x;
    if (idx >= LW * (DM / 2)) return;
    int l = idx / (DM / 2);
    int i = idx % (DM / 2);
    double ang = (double)l / pow(10000.0, (2.0 * i) / (double)DM);
    d_pe[l * DM + 2 * i]     = (float)sin(ang);
    d_pe[l * DM + 2 * i + 1] = (float)cos(ang);
}

// ---------------- fused CNN window encoder ----------------
__global__ __launch_bounds__(256) void cnn_kernel(
    const float* __restrict__ x,
    const float* __restrict__ w0, const float* __restrict__ b0,
    const float* __restrict__ w1, const float* __restrict__ b1,
    const float* __restrict__ w2, const float* __restrict__ b2)
{
    __shared__ float sx[256];
    __shared__ float a0[4 * 128];
    __shared__ float a1[16 * 64];
    __shared__ float sw0[28];
    __shared__ float sw1[448];
    __shared__ float sw2t[112 * 64];
    __shared__ float sb0[4], sb1[16], sb2[64];

    int win = blockIdx.x;
    int tid = threadIdx.x;

    sx[tid] = x[win * 256 + tid];
    if (tid < 28) sw0[tid] = w0[tid];
    if (tid < 4)  sb0[tid] = b0[tid];
    for (int i = tid; i < 448; i += 256) sw1[i] = w1[i];
    if (tid < 16) sb1[tid] = b1[tid];
    for (int i = tid; i < 7168; i += 256) {
        int c = i / 112, r = i % 112;
        sw2t[r * 64 + c] = w2[i];
    }
    if (tid < 64) sb2[tid] = b2[tid];
    __syncthreads();

    for (int it = tid; it < 4 * 128; it += 256) {
        int c = it >> 7, p = it & 127;
        float acc0 = sb0[c], acc1 = sb0[c];
        #pragma unroll
        for (int k = 0; k < 7; k++) {
            float wv = sw0[c * 7 + k];
            int i0 = 2 * p + k - 3, i1 = i0 + 1;
            if (i0 >= 0 && i0 < 256) acc0 += sx[i0] * wv;
            if (i1 >= 0 && i1 < 256) acc1 += sx[i1] * wv;
        }
        a0[c * 128 + p] = fmaxf(fmaxf(acc0, acc1), 0.f);
    }
    __syncthreads();

    for (int it = tid; it < 16 * 64; it += 256) {
        int c = it >> 6, p = it & 63;
        float acc0 = sb1[c], acc1 = sb1[c];
        for (int ci = 0; ci < 4; ci++) {
            const float* wrow = &sw1[(c * 4 + ci) * 7];
            const float* arow = &a0[ci * 128];
            #pragma unroll
            for (int k = 0; k < 7; k++) {
                float wv = wrow[k];
                int i0 = 2 * p + k - 3, i1 = i0 + 1;
                if (i0 >= 0 && i0 < 128) acc0 += arow[i0] * wv;
                if (i1 >= 0 && i1 < 128) acc1 += arow[i1] * wv;
            }
        }
        a1[c * 64 + p] = fmaxf(fmaxf(acc0, acc1), 0.f);
    }
    __syncthreads();

    {
        int c = tid & 63, g = tid >> 6;
        float acc0[8], acc1[8];
        #pragma unroll
        for (int p = 0; p < 8; p++) { acc0[p] = sb2[c]; acc1[p] = sb2[c]; }
        int base = 16 * g - 3;
        for (int ci = 0; ci < 16; ci++) {
            float xin[22];
            #pragma unroll
            for (int j = 0; j < 22; j++) {
                int idx = base + j;
                xin[j] = (idx >= 0 && idx < 64) ? a1[ci * 64 + idx] : 0.f;
            }
            float wv[7];
            #pragma unroll
            for (int k = 0; k < 7; k++) wv[k] = sw2t[(ci * 7 + k) * 64 + c];
            #pragma unroll
            for (int p = 0; p < 8; p++) {
                #pragma unroll
                for (int k = 0; k < 7; k++) {
                    acc0[p] += wv[k] * xin[2 * p + k];
                    acc1[p] += wv[k] * xin[2 * p + k + 1];
                }
            }
        }
        __half* dst = h_feat + (size_t)win * 2048 + c * 32 + g * 8;
        #pragma unroll
        for (int p = 0; p < 4; p++) {
            float e0 = fmaxf(fmaxf(acc0[2*p],   acc1[2*p]),   0.f);
            float e1 = fmaxf(fmaxf(acc0[2*p+1], acc1[2*p+1]), 0.f);
            *(__half2*)(dst + 2 * p) = __floats2half2_rn(e0, e1);
        }
    }
}

// ---------------- tensor-core attention: one block per (n,h), 8 warps ----------------
// S = Q K^T (fp16 mma, fp32 acc), softmax in fragments, P->smem fp16, O = P V (ldsm.trans B)
#define AROW  112                 // Q/K/V row stride bytes (56 halfs)
#define PROW  272                 // P row stride bytes (136 halfs)
#define ASM_Q 0
#define ASM_K 14336
#define ASM_V 28672
#define ASM_P 43008
#define ATTN_SMEM (43008 + 128*PROW)   // 77824

__global__ __launch_bounds__(256) void attn_kernel(
    const __half* __restrict__ q, const __half* __restrict__ k,
    const __half* __restrict__ v, __half* __restrict__ o)
{
    extern __shared__ char asmem[];
    uint32_t sb = smem_u32(asmem);
    int n = blockIdx.x, h = blockIdx.y;
    int tid = threadIdx.x, lane = tid & 31, wid = tid >> 5;

    // load Q,K,V tiles: 128 rows x 48 halfs, 6x16B per row
    for (int f = tid; f < 768; f += 256) {
        int s = f / 6, j = f % 6;
        size_t g = (size_t)(n * 128 + s) * DM + h * 48 + j * 8;
        cp16(sb + ASM_Q + s * AROW + j * 16, q + g);
        cp16(sb + ASM_K + s * AROW + j * 16, k + g);
        cp16(sb + ASM_V + s * AROW + j * 16, v + g);
    }
    cp_commit();
    cp_wait<0>();
    __syncthreads();

    // ---- S = Q K^T : warp owns 16 query rows (wid*16..+15), all 128 keys ----
    float c[16][4];
    #pragma unroll
    for (int i = 0; i < 16; i++)
        #pragma unroll
        for (int j = 0; j < 4; j++) c[i][j] = 0.f;

    uint32_t qaddr = sb + ASM_Q + (wid * 16 + (lane & 15)) * AROW + (lane >> 4) * 16;
    #pragma unroll
    for (int ks = 0; ks < 3; ks++) {           // K(=48) in 3 k16 steps
        uint32_t af[4];
        ldsm4(af, qaddr + ks * 32);
        #pragma unroll
        for (int nt2 = 0; nt2 < 8; nt2++) {    // 8 n16 groups = 128 keys
            uint32_t bf[4];
            ldsm4(bf, sb + ASM_K + (nt2 * 16 + (lane & 15)) * AROW + (lane >> 4) * 16 + ks * 32);
            mma16(c[nt2 * 2],     af, bf[0], bf[2]);
            mma16(c[nt2 * 2 + 1], af, bf[1], bf[3]);
        }
    }

    // ---- softmax over 128 keys (rows r0 = wid*16 + lane>>2, r1 = r0+8) ----
    const float temp = 0.14433756729740643f;   // 1/sqrt(48)
    float mx0 = -1e30f, mx1 = -1e30f;
    #pragma unroll
    for (int nt = 0; nt < 16; nt++) {
        c[nt][0] *= temp; c[nt][1] *= temp; c[nt][2] *= temp; c[nt][3] *= temp;
        mx0 = fmaxf(mx0, fmaxf(c[nt][0], c[nt][1]));
        mx1 = fmaxf(mx1, fmaxf(c[nt][2], c[nt][3]));
    }
    #pragma unroll
    for (int d2 = 1; d2 <= 2; d2 <<= 1) {
        mx0 = fmaxf(mx0, __shfl_xor_sync(0xFFFFFFFFu, mx0, d2));
        mx1 = fmaxf(mx1, __shfl_xor_sync(0xFFFFFFFFu, mx1, d2));
    }
    float s0 = 0.f, s1 = 0.f;
    int prow0 = wid * 16 + (lane >> 2);
    int pcol  = (lane & 3) * 2;
    #pragma unroll
    for (int nt = 0; nt < 16; nt++) {
        float p0 = __expf(c[nt][0] - mx0);
        float p1 = __expf(c[nt][1] - mx0);
        float p2 = __expf(c[nt][2] - mx1);
        float p3 = __expf(c[nt][3] - mx1);
        s0 += p0 + p1; s1 += p2 + p3;
        *(__half2*)(asmem + ASM_P + prow0 * PROW + (nt * 8 + pcol) * 2)       = __floats2half2_rn(p0, p1);
        *(__half2*)(asmem + ASM_P + (prow0 + 8) * PROW + (nt * 8 + pcol) * 2) = __floats2half2_rn(p2, p3);
    }
    #pragma unroll
    for (int d2 = 1; d2 <= 2; d2 <<= 1) {
        s0 += __shfl_xor_sync(0xFFFFFFFFu, s0, d2);
        s1 += __shfl_xor_sync(0xFFFFFFFFu, s1, d2);
    }
    float inv0 = 1.0f / s0, inv1 = 1.0f / s1;
    __syncwarp();   // warp reads back only its own 16 P rows

    // ---- O = P V : M=16 (warp rows), N=48, K=128 ----
    float oacc[6][4];
    #pragma unroll
    for (int i = 0; i < 6; i++)
        #pragma unroll
        for (int j = 0; j < 4; j++) oacc[i][j] = 0.f;

    uint32_t paddr = sb + ASM_P + (wid * 16 + (lane & 15)) * PROW + (lane >> 4) * 16;
    #pragma unroll
    for (int ks = 0; ks < 8; ks++) {           // 128 seq in 8 k16 steps
        uint32_t af[4];
        ldsm4(af, paddr + ks * 32);
        #pragma unroll
        for (int nb = 0; nb < 3; nb++) {       // 48 head dims in 3 n16 groups
            uint32_t bf[4];
            ldsm4t(bf, sb + ASM_V + (ks * 16 + (lane & 15)) * AROW + nb * 32 + (lane >> 4) * 16);
            mma16(oacc[nb * 2],     af, bf[0], bf[1]);
            mma16(oacc[nb * 2 + 1], af, bf[2], bf[3]);
        }
    }

    // ---- store ----
    __half* op0 = o + (size_t)(n * 128 + prow0) * DM + h * 48 + pcol;
    __half* op1 = op0 + (size_t)8 * DM;
    #pragma unroll
    for (int nt = 0; nt < 6; nt++) {
        *(__half2*)(op0 + nt * 8) = __floats2half2_rn(oacc[nt][0] * inv0, oacc[nt][1] * inv0);
        *(__half2*)(op1 + nt * 8) = __floats2half2_rn(oacc[nt][2] * inv1, oacc[nt][3] * inv1);
    }
}

// ---------------- layernorm (384): warp per row, 8 rows per block; half in/out ----------------
__global__ __launch_bounds__(256) void ln_kernel(
    const __half* __restrict__ in, const float* __restrict__ g,
    const float* __restrict__ b, __half* __restrict__ out)
{
    int row = blockIdx.x * 8 + (threadIdx.x >> 5);
    int lane = threadIdx.x & 31;
    const __half2* rp = (const __half2*)(in + (size_t)row * DM);
    int b2 = lane * 2;

    float2 f0 = __half22float2(rp[b2]),       f1 = __half22float2(rp[b2 + 1]);
    float2 f2 = __half22float2(rp[b2 + 64]),  f3 = __half22float2(rp[b2 + 65]);
    float2 f4 = __half22float2(rp[b2 + 128]), f5 = __half22float2(rp[b2 + 129]);

    float s = f0.x + f0.y + f1.x + f1.y + f2.x + f2.y + f3.x + f3.y + f4.x + f4.y + f5.x + f5.y;
    #pragma unroll
    for (int o2 = 16; o2; o2 >>= 1) s += __shfl_xor_sync(0xFFFFFFFFu, s, o2);
    float mean = s * (1.0f / 384.0f);

    float d0x = f0.x - mean, d0y = f0.y - mean, d1x = f1.x - mean, d1y = f1.y - mean;
    float d2x = f2.x - mean, d2y = f2.y - mean, d3x = f3.x - mean, d3y = f3.y - mean;
    float d4x = f4.x - mean, d4y = f4.y - mean, d5x = f5.x - mean, d5y = f5.y - mean;
    float q = d0x*d0x + d0y*d0y + d1x*d1x + d1y*d1y + d2x*d2x + d2y*d2y
            + d3x*d3x + d3y*d3y + d4x*d4x + d4y*d4y + d5x*d5x + d5y*d5y;
    #pragma unroll
    for (int o2 = 16; o2; o2 >>= 1) q += __shfl_xor_sync(0xFFFFFFFFu, q, o2);
    float inv = rsqrtf(q * (1.0f / 384.0f) + 1e-5f);

    float4 g0 = *(const float4*)(g + lane * 4);
    float4 g1 = *(const float4*)(g + lane * 4 + 128);
    float4 g2 = *(const float4*)(g + lane * 4 + 256);
    float4 b0 = *(const float4*)(b + lane * 4);
    float4 b1 = *(const float4*)(b + lane * 4 + 128);
    float4 b2v = *(const float4*)(b + lane * 4 + 256);

    __half2* op = (__half2*)(out + (size_t)row * DM);
    op[b2]       = __floats2half2_rn(d0x*inv*g0.x + b0.x,  d0y*inv*g0.y + b0.y);
    op[b2 + 1]   = __floats2half2_rn(d1x*inv*g0.z + b0.z,  d1y*inv*g0.w + b0.w);
    op[b2 + 64]  = __floats2half2_rn(d2x*inv*g1.x + b1.x,  d2y*inv*g1.y + b1.y);
    op[b2 + 65]  = __floats2half2_rn(d3x*inv*g1.z + b1.z,  d3y*inv*g1.w + b1.w);
    op[b2 + 128] = __floats2half2_rn(d4x*inv*g2.x + b2v.x, d4y*inv*g2.y + b2v.y);
    op[b2 + 129] = __floats2half2_rn(d5x*inv*g2.z + b2v.z, d5y*inv*g2.w + b2v.w);
}

// ---------------- mean-pool over L + classifier ----------------
__global__ __launch_bounds__(384) void cls_kernel(
    const __half* __restrict__ t, const float* __restrict__ w,
    const float* __restrict__ b, float* __restrict__ out)
{
    __shared__ float red[384];
    int n = blockIdx.x, d = threadIdx.x;
    float s = 0.f;
    for (int l = 0; l < 128; l++) s += __half2float(t[(size_t)(n * 128 + l) * DM + d]);
    red[d] = (s * (1.0f / 128.0f)) * w[d];
    __syncthreads();
    if (d < 128) red[d] += red[d + 128] + red[d + 256];
    __syncthreads();
    for (int st = 64; st > 0; st >>= 1) { if (d < st) red[d] += red[d + st]; __syncthreads(); }
    if (d == 0) out[n] = red[0] + b[0];
}

// ---------------- launcher ----------------
extern "C" void kernel_launch(void* const* d_in, const int* in_sizes, int n_in,
                              void* d_out, int out_size)
{
    const float* x   = (const float*)d_in[0];
    const float* cw0 = (const float*)d_in[1];
    const float* cb0 = (const float*)d_in[2];
    const float* cw1 = (const float*)d_in[3];
    const float* cb1 = (const float*)d_in[4];
    const float* cw2 = (const float*)d_in[5];
    const float* cb2 = (const float*)d_in[6];
    const float* ew  = (const float*)d_in[7];
    const float* eb  = (const float*)d_in[8];

    const float *Wq,*Wk,*Wv,*Wo,*W1,*W2,*bq,*bk,*bv,*bo,*b1,*b2;
    if (in_sizes[10] == 1536) {
        Wq=(const float*)d_in[9];  bq=(const float*)d_in[10];
        Wk=(const float*)d_in[11]; bk=(const float*)d_in[12];
        Wv=(const float*)d_in[13]; bv=(const float*)d_in[14];
        Wo=(const float*)d_in[15]; bo=(const float*)d_in[16];
        W1=(const float*)d_in[17]; b1=(const float*)d_in[18];
        W2=(const float*)d_in[19]; b2=(const float*)d_in[20];
    } else {
        Wq=(const float*)d_in[9];  Wk=(const float*)d_in[10];
        Wv=(const float*)d_in[11]; Wo=(const float*)d_in[12];
        W1=(const float*)d_in[13]; W2=(const float*)d_in[14];
        bq=(const float*)d_in[15]; bk=(const float*)d_in[16];
        bv=(const float*)d_in[17]; bo=(const float*)d_in[18];
        b1=(const float*)d_in[19]; b2=(const float*)d_in[20];
    }
    const float* g1  = (const float*)d_in[21];
    const float* be1 = (const float*)d_in[22];
    const float* g2  = (const float*)d_in[23];
    const float* be2 = (const float*)d_in[24];
    const float* clw = (const float*)d_in[25];
    const float* clb = (const float*)d_in[26];
    float* out = (float*)d_out;

    __half *p_feat,*p_t,*p_q,*p_k,*p_v,*p_ao,*p_buf,*p_mid;
    __half *p_bte,*p_btq,*p_btk,*p_btv,*p_bto,*p_bt1,*p_bt2;
    float *p_pe;
    cudaGetSymbolAddress((void**)&p_feat, h_feat);
    cudaGetSymbolAddress((void**)&p_t,   h_t);
    cudaGetSymbolAddress((void**)&p_q,   h_q);
    cudaGetSymbolAddress((void**)&p_k,   h_k);
    cudaGetSymbolAddress((void**)&p_v,   h_v);
    cudaGetSymbolAddress((void**)&p_ao,  h_ao);
    cudaGetSymbolAddress((void**)&p_buf, h_buf);
    cudaGetSymbolAddress((void**)&p_mid, h_mid);
    cudaGetSymbolAddress((void**)&p_pe,  d_pe);
    cudaGetSymbolAddress((void**)&p_bte, h_bte);
    cudaGetSymbolAddress((void**)&p_btq, h_btq);
    cudaGetSymbolAddress((void**)&p_btk, h_btk);
    cudaGetSymbolAddress((void**)&p_btv, h_btv);
    cudaGetSymbolAddress((void**)&p_bto, h_bto);
    cudaGetSymbolAddress((void**)&p_bt1, h_bt1);
    cudaGetSymbolAddress((void**)&p_bt2, h_bt2);

    cudaFuncSetAttribute(attn_kernel, cudaFuncAttributeMaxDynamicSharedMemorySize, ATTN_SMEM);

    dim3 tb(32, 8);
    pe_kernel<<<(LW*(DM/2) + 255)/256, 256>>>();
    cnn_kernel<<<NWIN, 256>>>(x, cw0, cb0, cw1, cb1, cw2, cb2);
    transpose_h<<<dim3(FEATD/32, DM/32, 1), tb>>>(ew, p_bte, FEATD, DM);
    transpose_h_qkvo<<<dim3(DM/32, DM/32, 16), tb>>>(Wq, Wk, Wv, Wo,
                                                     p_btq, p_btk, p_btv, p_bto);
    transpose_h<<<dim3(DM/32, DFF/32, 4), tb>>>(W1, p_bt1, DM, DFF);
    // embed: t = h( relu(feat @ ew + eb) + pe )
    gemm_h<<<dim3(DM/128, NWIN/64), 256, GSMEM>>>(p_feat, p_bte, eb, p_pe, p_t, FEATD, DM, 3);
    transpose_h<<<dim3(DFF/32, DM/32, 4), tb>>>(W2, p_bt2, DFF, DM);

    for (int i = 0; i < 4; i++) {
        gemm_h_qkv<<<dim3(9, NWIN/64), 256, GSMEM>>>(
            p_t,
            p_btq + (size_t)i*DM*DM, p_btk + (size_t)i*DM*DM, p_btv + (size_t)i*DM*DM,
            bq + i*DM, bk + i*DM, bv + i*DM,
            p_q, p_k, p_v);

        attn_kernel<<<dim3(NB, HH), 256, ATTN_SMEM>>>(p_q, p_k, p_v, p_ao);

        gemm_h<<<dim3(DM/128, NWIN/64), 256, GSMEM>>>(
            p_ao, p_bto + (size_t)i*DM*DM, bo + i*DM, p_t, p_buf, DM, DM, 2);
        ln_kernel<<<NWIN/8, 256>>>(p_buf, g1 + i*DM, be1 + i*DM, p_t);

        gemm_h<<<dim3(DFF/128, NWIN/64), 256, GSMEM>>>(
            p_t, p_bt1 + (size_t)i*DFF*DM, b1 + i*DFF, nullptr, p_mid, DM, DFF, 1);
        gemm_h<<<dim3(DM/128, NWIN/64), 256, GSMEM>>>(
            p_mid, p_bt2 + (size_t)i*DM*DFF, b2 + i*DM, p_t, p_buf, DFF, DM, 2);
        ln_kernel<<<NWIN/8, 256>>>(p_buf, g2 + i*DM, be2 + i*DM, p_t);
    }

    cls_kernel<<<NB, 384>>>(p_t, clw, clb, out);
}

// round 14
// speedup vs baseline: 1.5984x; 1.5984x over previous
#include <cuda_runtime.h>
#include <cuda_fp16.h>
#include <math.h>
#include <stdint.h>

// ---------------- problem constants ----------------
#define NB    64
#define LW    128
#define DM    384
#define HH    8
#define DFF   1536
#define NWIN  (NB*LW)     // 8192
#define FEATD 2048

// ---------------- scratch (device globals, alloc-free) ----------------
__device__ __half h_feat[NWIN*FEATD];
__device__ __half h_t  [NWIN*DM];
__device__ __half h_q  [NWIN*DM];
__device__ __half h_k  [NWIN*DM];
__device__ __half h_v  [NWIN*DM];
__device__ __half h_ao [NWIN*DM];
__device__ __half h_buf[NWIN*DM];
__device__ __half h_mid[NWIN*DFF];
__device__ float  d_pe [LW*DM];
__device__ __half h_bte[DM*FEATD];
__device__ __half h_btq[4][DM*DM];
__device__ __half h_btk[4][DM*DM];
__device__ __half h_btv[4][DM*DM];
__device__ __half h_bto[4][DM*DM];
__device__ __half h_bt1[4][DFF*DM];
__device__ __half h_bt2[4][DM*DFF];

// ---------------- helpers ----------------
__device__ __forceinline__ uint32_t smem_u32(const void* p) {
    uint32_t a;
    asm("{ .reg .u64 t; cvta.to.shared.u64 t, %1; cvt.u32.u64 %0, t; }" : "=r"(a) : "l"(p));
    return a;
}
__device__ __forceinline__ void cp16(uint32_t s, const void* g) {
    asm volatile("cp.async.cg.shared.global [%0], [%1], 16;" :: "r"(s), "l"(g));
}
__device__ __forceinline__ void cp_commit() { asm volatile("cp.async.commit_group;"); }
template<int N> __device__ __forceinline__ void cp_wait() {
    asm volatile("cp.async.wait_group %0;" :: "n"(N));
}
__device__ __forceinline__ void ldsm4(uint32_t* r, uint32_t addr) {
    asm volatile("ldmatrix.sync.aligned.m8n8.x4.shared.b16 {%0,%1,%2,%3}, [%4];"
        : "=r"(r[0]), "=r"(r[1]), "=r"(r[2]), "=r"(r[3]) : "r"(addr));
}
__device__ __forceinline__ void ldsm4t(uint32_t* r, uint32_t addr) {
    asm volatile("ldmatrix.sync.aligned.m8n8.x4.trans.shared.b16 {%0,%1,%2,%3}, [%4];"
        : "=r"(r[0]), "=r"(r[1]), "=r"(r[2]), "=r"(r[3]) : "r"(addr));
}
// m16n8k16 fp16 mma, fp32 accumulate
__device__ __forceinline__ void mma16(float* c, const uint32_t* a, uint32_t b0, uint32_t b1) {
    asm volatile("mma.sync.aligned.m16n8k16.row.col.f32.f16.f16.f32 "
        "{%0,%1,%2,%3}, {%4,%5,%6,%7}, {%8,%9}, {%0,%1,%2,%3};"
        : "+f"(c[0]), "+f"(c[1]), "+f"(c[2]), "+f"(c[3])
        : "r"(a[0]), "r"(a[1]), "r"(a[2]), "r"(a[3]), "r"(b0), "r"(b1));
}

// SMEM per stage: A [64][40] halfs + B [128][40] halfs (rows 32 -> pad 40 halfs = 80 B)
#define ROWB    80
#define ATILEB  (64*ROWB)       // 5120
#define BTILEB  (128*ROWB)      // 10240
#define STAGEB  (ATILEB+BTILEB) // 15360
#define GSMEM   (2*STAGEB)      // 30720 (2-stage, round-10 proven)

// ---------------- fp16 mma GEMM core: C tile 64x128, K chunks of 32, 2-stage ----------------
// epi: 0=+bias ; 1=relu(+bias) ; 2=+bias+extra_half[m*ldc+c] ; 3=relu(+bias)+pe_f32[(m&127)*ldc+c]
__device__ __forceinline__ void gemm_core(
    const __half* __restrict__ A, const __half* __restrict__ BtBlk,
    const float* __restrict__ bias, const void* __restrict__ extra,
    __half* __restrict__ C, int K, int ldc, int epi, int row0, int col0)
{
    extern __shared__ float sm[];
    uint32_t sbase = smem_u32(sm);
    int tid = threadIdx.x;

    int lrow = tid >> 2, lc = tid & 3;
    const __half* Ag  = A + (size_t)(row0 + lrow) * K + lc * 8;
    const __half* Bg0 = BtBlk + (size_t)lrow * K + lc * 8;
    const __half* Bg1 = BtBlk + (size_t)(lrow + 64) * K + lc * 8;
    uint32_t sA  = sbase + lrow * ROWB + lc * 16;
    uint32_t sB0 = sbase + ATILEB + lrow * ROWB + lc * 16;
    uint32_t sB1 = sB0 + 64 * ROWB;
    int nk = K >> 5;

    // prologue: chunk 0 -> slot 0
    cp16(sA, Ag); cp16(sB0, Bg0); cp16(sB1, Bg1);
    cp_commit();

    int lane = tid & 31, w = tid >> 5, wm = w & 1, wn = w >> 1;
    uint32_t aoff = sbase + (wm * 32 + (lane & 15)) * ROWB + (lane >> 4) * 16;
    uint32_t boff = sbase + ATILEB + (wn * 32 + (lane & 15)) * ROWB + (lane >> 4) * 16;

    float c[2][4][4];
    #pragma unroll
    for (int i = 0; i < 2; i++)
        #pragma unroll
        for (int j = 0; j < 4; j++)
            #pragma unroll
            for (int q = 0; q < 4; q++) c[i][j][q] = 0.f;

    for (int kc = 0; kc < nk; kc++) {
        cp_wait<0>();
        __syncthreads();
        if (kc + 1 < nk) {
            uint32_t off = ((kc + 1) & 1) * STAGEB;
            int ho = (kc + 1) * 32;
            cp16(sA + off,  Ag + ho);
            cp16(sB0 + off, Bg0 + ho);
            cp16(sB1 + off, Bg1 + ho);
            cp_commit();
        }
        uint32_t st = (kc & 1) * STAGEB;
        uint32_t ab = aoff + st;
        uint32_t bb = boff + st;
        #pragma unroll
        for (int ks = 0; ks < 2; ks++) {           // two k16 steps per 32-chunk
            uint32_t af[2][4], bf[2][4];
            #pragma unroll
            for (int mf = 0; mf < 2; mf++)
                ldsm4(af[mf], ab + mf * 16 * ROWB + ks * 32);
            #pragma unroll
            for (int np = 0; np < 2; np++)
                ldsm4(bf[np], bb + np * 16 * ROWB + ks * 32);
            #pragma unroll
            for (int mf = 0; mf < 2; mf++)
                #pragma unroll
                for (int nf = 0; nf < 4; nf++) {
                    int np = nf >> 1, sub = nf & 1;
                    mma16(c[mf][nf], af[mf], bf[np][sub], bf[np][sub + 2]);
                }
        }
    }

    // epilogue -> half
    #pragma unroll
    for (int mf = 0; mf < 2; mf++) {
        #pragma unroll
        for (int half = 0; half < 2; half++) {
            int r = row0 + wm * 32 + mf * 16 + (lane >> 2) + half * 8;
            #pragma unroll
            for (int nf = 0; nf < 4; nf++) {
                int col = col0 + wn * 32 + nf * 8 + (lane & 3) * 2;
                float v0 = c[mf][nf][half * 2 + 0] + bias[col];
                float v1 = c[mf][nf][half * 2 + 1] + bias[col + 1];
                if (epi == 1) { v0 = fmaxf(v0, 0.f); v1 = fmaxf(v1, 0.f); }
                else if (epi == 2) {
                    __half2 e = *(const __half2*)((const __half*)extra + (size_t)r * ldc + col);
                    v0 += __low2float(e); v1 += __high2float(e);
                } else if (epi == 3) {
                    const float* ex = (const float*)extra + (size_t)(r & (LW - 1)) * ldc;
                    v0 = fmaxf(v0, 0.f) + ex[col];
                    v1 = fmaxf(v1, 0.f) + ex[col + 1];
                }
                *(__half2*)(C + (size_t)r * ldc + col) = __floats2half2_rn(v0, v1);
            }
        }
    }
}

__global__ __launch_bounds__(256, 3) void gemm_h(
    const __half* __restrict__ A, const __half* __restrict__ Bt,
    const float* __restrict__ bias, const void* __restrict__ extra,
    __half* __restrict__ C, int K, int N, int epi)
{
    gemm_core(A, Bt + (size_t)blockIdx.x * 128 * K, bias, extra, C, K, N, epi,
              blockIdx.y * 64, blockIdx.x * 128);
}

__global__ __launch_bounds__(256, 3) void gemm_h_qkv(
    const __half* __restrict__ A,
    const __half* __restrict__ btq, const __half* __restrict__ btk, const __half* __restrict__ btv,
    const float* __restrict__ bqv, const float* __restrict__ bkv, const float* __restrict__ bvv,
    __half* __restrict__ q, __half* __restrict__ k, __half* __restrict__ v)
{
    int sel = blockIdx.x / 3, j = blockIdx.x % 3;
    const __half* Bt   = sel == 0 ? btq : (sel == 1 ? btk : btv);
    const float* bias  = sel == 0 ? bqv : (sel == 1 ? bkv : bvv);
    __half*      C     = sel == 0 ? q   : (sel == 1 ? k   : v);
    gemm_core(A, Bt + (size_t)j * 128 * DM, bias, nullptr, C, DM, DM, 0,
              blockIdx.y * 64, j * 128);
}

// ---------------- batched weight transpose -> fp16 ----------------
__global__ void transpose_h(const float* __restrict__ in, __half* __restrict__ out, int Kd, int Nd)
{
    size_t mstride = (size_t)Kd * Nd;
    in  += blockIdx.z * mstride;
    out += blockIdx.z * mstride;
    __shared__ float tile[32][33];
    int kb = blockIdx.x * 32, nb = blockIdx.y * 32;
    int tx = threadIdx.x, ty = threadIdx.y;
    #pragma unroll
    for (int j = 0; j < 32; j += 8)
        tile[ty + j][tx] = in[(size_t)(kb + ty + j) * Nd + nb + tx];
    __syncthreads();
    #pragma unroll
    for (int j = 0; j < 32; j += 8)
        out[(size_t)(nb + ty + j) * Kd + kb + tx] = __float2half_rn(tile[tx][ty + j]);
}

__global__ void transpose_h_qkvo(
    const float* __restrict__ Wq, const float* __restrict__ Wk,
    const float* __restrict__ Wv, const float* __restrict__ Wo,
    __half* __restrict__ oq, __half* __restrict__ ok,
    __half* __restrict__ ov, __half* __restrict__ oo)
{
    int z = blockIdx.z, sel = z >> 2, layer = z & 3;
    const float* in = (sel == 0 ? Wq : sel == 1 ? Wk : sel == 2 ? Wv : Wo)
                      + (size_t)layer * DM * DM;
    __half* out = (sel == 0 ? oq : sel == 1 ? ok : sel == 2 ? ov : oo)
                  + (size_t)layer * DM * DM;
    __shared__ float tile[32][33];
    int kb = blockIdx.x * 32, nb = blockIdx.y * 32;
    int tx = threadIdx.x, ty = threadIdx.y;
    #pragma unroll
    for (int j = 0; j < 32; j += 8)
        tile[ty + j][tx] = in[(size_t)(kb + ty + j) * DM + nb + tx];
    __syncthreads();
    #pragma unroll
    for (int j = 0; j < 32; j += 8)
        out[(size_t)(nb + ty + j) * DM + kb + tx] = __float2half_rn(tile[tx][ty + j]);
}

// ---------------- positional encoding ----------------
__global__ void pe_kernel() {
    int idx = blockIdx.x * blockDim.x + threadIdx.x;
    if (idx >= LW * (DM / 2)) return;
    int l = idx / (DM / 2);
    int i = idx % (DM / 2);
    double ang = (double)l / pow(10000.0, (2.0 * i) / (double)DM);
    d_pe[l * DM + 2 * i]     = (float)sin(ang);
    d_pe[l * DM + 2 * i + 1] = (float)cos(ang);
}

// ---------------- fused CNN window encoder ----------------
__global__ __launch_bounds__(256) void cnn_kernel(
    const float* __restrict__ x,
    const float* __restrict__ w0, const float* __restrict__ b0,
    const float* __restrict__ w1, const float* __restrict__ b1,
    const float* __restrict__ w2, const float* __restrict__ b2)
{
    __shared__ float sx[256];
    __shared__ float a0[4 * 128];
    __shared__ float a1[16 * 64];
    __shared__ float sw0[28];
    __shared__ float sw1[448];
    __shared__ float sw2t[112 * 64];
    __shared__ float sb0[4], sb1[16], sb2[64];

    int win = blockIdx.x;
    int tid = threadIdx.x;

    sx[tid] = x[win * 256 + tid];
    if (tid < 28) sw0[tid] = w0[tid];
    if (tid < 4)  sb0[tid] = b0[tid];
    for (int i = tid; i < 448; i += 256) sw1[i] = w1[i];
    if (tid < 16) sb1[tid] = b1[tid];
    for (int i = tid; i < 7168; i += 256) {
        int c = i / 112, r = i % 112;
        sw2t[r * 64 + c] = w2[i];
    }
    if (tid < 64) sb2[tid] = b2[tid];
    __syncthreads();

    for (int it = tid; it < 4 * 128; it += 256) {
        int c = it >> 7, p = it & 127;
        float acc0 = sb0[c], acc1 = sb0[c];
        #pragma unroll
        for (int k = 0; k < 7; k++) {
            float wv = sw0[c * 7 + k];
            int i0 = 2 * p + k - 3, i1 = i0 + 1;
            if (i0 >= 0 && i0 < 256) acc0 += sx[i0] * wv;
            if (i1 >= 0 && i1 < 256) acc1 += sx[i1] * wv;
        }
        a0[c * 128 + p] = fmaxf(fmaxf(acc0, acc1), 0.f);
    }
    __syncthreads();

    for (int it = tid; it < 16 * 64; it += 256) {
        int c = it >> 6, p = it & 63;
        float acc0 = sb1[c], acc1 = sb1[c];
        for (int ci = 0; ci < 4; ci++) {
            const float* wrow = &sw1[(c * 4 + ci) * 7];
            const float* arow = &a0[ci * 128];
            #pragma unroll
            for (int k = 0; k < 7; k++) {
                float wv = wrow[k];
                int i0 = 2 * p + k - 3, i1 = i0 + 1;
                if (i0 >= 0 && i0 < 128) acc0 += arow[i0] * wv;
                if (i1 >= 0 && i1 < 128) acc1 += arow[i1] * wv;
            }
        }
        a1[c * 64 + p] = fmaxf(fmaxf(acc0, acc1), 0.f);
    }
    __syncthreads();

    {
        int c = tid & 63, g = tid >> 6;
        float acc0[8], acc1[8];
        #pragma unroll
        for (int p = 0; p < 8; p++) { acc0[p] = sb2[c]; acc1[p] = sb2[c]; }
        int base = 16 * g - 3;
        for (int ci = 0; ci < 16; ci++) {
            float xin[22];
            #pragma unroll
            for (int j = 0; j < 22; j++) {
                int idx = base + j;
                xin[j] = (idx >= 0 && idx < 64) ? a1[ci * 64 + idx] : 0.f;
            }
            float wv[7];
            #pragma unroll
            for (int k = 0; k < 7; k++) wv[k] = sw2t[(ci * 7 + k) * 64 + c];
            #pragma unroll
            for (int p = 0; p < 8; p++) {
                #pragma unroll
                for (int k = 0; k < 7; k++) {
                    acc0[p] += wv[k] * xin[2 * p + k];
                    acc1[p] += wv[k] * xin[2 * p + k + 1];
                }
            }
        }
        __half* dst = h_feat + (size_t)win * 2048 + c * 32 + g * 8;
        #pragma unroll
        for (int p = 0; p < 4; p++) {
            float e0 = fmaxf(fmaxf(acc0[2*p],   acc1[2*p]),   0.f);
            float e1 = fmaxf(fmaxf(acc0[2*p+1], acc1[2*p+1]), 0.f);
            *(__half2*)(dst + 2 * p) = __floats2half2_rn(e0, e1);
        }
    }
}

// ---------------- tensor-core attention: one block per (n,h), 8 warps ----------------
#define AROW  112                 // Q/K/V row stride bytes (56 halfs)
#define PROW  272                 // P row stride bytes (136 halfs)
#define ASM_Q 0
#define ASM_K 14336
#define ASM_V 28672
#define ASM_P 43008
#define ATTN_SMEM (43008 + 128*PROW)   // 77824

__global__ __launch_bounds__(256) void attn_kernel(
    const __half* __restrict__ q, const __half* __restrict__ k,
    const __half* __restrict__ v, __half* __restrict__ o)
{
    extern __shared__ char asmem[];
    uint32_t sb = smem_u32(asmem);
    int n = blockIdx.x, h = blockIdx.y;
    int tid = threadIdx.x, lane = tid & 31, wid = tid >> 5;

    // load Q,K,V tiles: 128 rows x 48 halfs, 6x16B per row
    for (int f = tid; f < 768; f += 256) {
        int s = f / 6, j = f % 6;
        size_t g = (size_t)(n * 128 + s) * DM + h * 48 + j * 8;
        cp16(sb + ASM_Q + s * AROW + j * 16, q + g);
        cp16(sb + ASM_K + s * AROW + j * 16, k + g);
        cp16(sb + ASM_V + s * AROW + j * 16, v + g);
    }
    cp_commit();
    cp_wait<0>();
    __syncthreads();

    // ---- S = Q K^T ----
    float c[16][4];
    #pragma unroll
    for (int i = 0; i < 16; i++)
        #pragma unroll
        for (int j = 0; j < 4; j++) c[i][j] = 0.f;

    uint32_t qaddr = sb + ASM_Q + (wid * 16 + (lane & 15)) * AROW + (lane >> 4) * 16;
    #pragma unroll
    for (int ks = 0; ks < 3; ks++) {
        uint32_t af[4];
        ldsm4(af, qaddr + ks * 32);
        #pragma unroll
        for (int nt2 = 0; nt2 < 8; nt2++) {
            uint32_t bf[4];
            ldsm4(bf, sb + ASM_K + (nt2 * 16 + (lane & 15)) * AROW + (lane >> 4) * 16 + ks * 32);
            mma16(c[nt2 * 2],     af, bf[0], bf[2]);
            mma16(c[nt2 * 2 + 1], af, bf[1], bf[3]);
        }
    }

    // ---- softmax ----
    const float temp = 0.14433756729740643f;   // 1/sqrt(48)
    float mx0 = -1e30f, mx1 = -1e30f;
    #pragma unroll
    for (int nt = 0; nt < 16; nt++) {
        c[nt][0] *= temp; c[nt][1] *= temp; c[nt][2] *= temp; c[nt][3] *= temp;
        mx0 = fmaxf(mx0, fmaxf(c[nt][0], c[nt][1]));
        mx1 = fmaxf(mx1, fmaxf(c[nt][2], c[nt][3]));
    }
    #pragma unroll
    for (int d2 = 1; d2 <= 2; d2 <<= 1) {
        mx0 = fmaxf(mx0, __shfl_xor_sync(0xFFFFFFFFu, mx0, d2));
        mx1 = fmaxf(mx1, __shfl_xor_sync(0xFFFFFFFFu, mx1, d2));
    }
    float s0 = 0.f, s1 = 0.f;
    int prow0 = wid * 16 + (lane >> 2);
    int pcol  = (lane & 3) * 2;
    #pragma unroll
    for (int nt = 0; nt < 16; nt++) {
        float p0 = __expf(c[nt][0] - mx0);
        float p1 = __expf(c[nt][1] - mx0);
        float p2 = __expf(c[nt][2] - mx1);
        float p3 = __expf(c[nt][3] - mx1);
        s0 += p0 + p1; s1 += p2 + p3;
        *(__half2*)(asmem + ASM_P + prow0 * PROW + (nt * 8 + pcol) * 2)       = __floats2half2_rn(p0, p1);
        *(__half2*)(asmem + ASM_P + (prow0 + 8) * PROW + (nt * 8 + pcol) * 2) = __floats2half2_rn(p2, p3);
    }
    #pragma unroll
    for (int d2 = 1; d2 <= 2; d2 <<= 1) {
        s0 += __shfl_xor_sync(0xFFFFFFFFu, s0, d2);
        s1 += __shfl_xor_sync(0xFFFFFFFFu, s1, d2);
    }
    float inv0 = 1.0f / s0, inv1 = 1.0f / s1;
    __syncwarp();

    // ---- O = P V ----
    float oacc[6][4];
    #pragma unroll
    for (int i = 0; i < 6; i++)
        #pragma unroll
        for (int j = 0; j < 4; j++) oacc[i][j] = 0.f;

    uint32_t paddr = sb + ASM_P + (wid * 16 + (lane & 15)) * PROW + (lane >> 4) * 16;
    #pragma unroll
    for (int ks = 0; ks < 8; ks++) {
        uint32_t af[4];
        ldsm4(af, paddr + ks * 32);
        #pragma unroll
        for (int nb = 0; nb < 3; nb++) {
            uint32_t bf[4];
            ldsm4t(bf, sb + ASM_V + (ks * 16 + (lane & 15)) * AROW + nb * 32 + (lane >> 4) * 16);
            mma16(oacc[nb * 2],     af, bf[0], bf[1]);
            mma16(oacc[nb * 2 + 1], af, bf[2], bf[3]);
        }
    }

    // ---- store ----
    __half* op0 = o + (size_t)(n * 128 + prow0) * DM + h * 48 + pcol;
    __half* op1 = op0 + (size_t)8 * DM;
    #pragma unroll
    for (int nt = 0; nt < 6; nt++) {
        *(__half2*)(op0 + nt * 8) = __floats2half2_rn(oacc[nt][0] * inv0, oacc[nt][1] * inv0);
        *(__half2*)(op1 + nt * 8) = __floats2half2_rn(oacc[nt][2] * inv1, oacc[nt][3] * inv1);
    }
}

// ---------------- layernorm (384): warp per row, 8 rows per block; half in/out ----------------
__global__ __launch_bounds__(256) void ln_kernel(
    const __half* __restrict__ in, const float* __restrict__ g,
    const float* __restrict__ b, __half* __restrict__ out)
{
    int row = blockIdx.x * 8 + (threadIdx.x >> 5);
    int lane = threadIdx.x & 31;
    const __half2* rp = (const __half2*)(in + (size_t)row * DM);
    int b2 = lane * 2;

    float2 f0 = __half22float2(rp[b2]),       f1 = __half22float2(rp[b2 + 1]);
    float2 f2 = __half22float2(rp[b2 + 64]),  f3 = __half22float2(rp[b2 + 65]);
    float2 f4 = __half22float2(rp[b2 + 128]), f5 = __half22float2(rp[b2 + 129]);

    float s = f0.x + f0.y + f1.x + f1.y + f2.x + f2.y + f3.x + f3.y + f4.x + f4.y + f5.x + f5.y;
    #pragma unroll
    for (int o2 = 16; o2; o2 >>= 1) s += __shfl_xor_sync(0xFFFFFFFFu, s, o2);
    float mean = s * (1.0f / 384.0f);

    float d0x = f0.x - mean, d0y = f0.y - mean, d1x = f1.x - mean, d1y = f1.y - mean;
    float d2x = f2.x - mean, d2y = f2.y - mean, d3x = f3.x - mean, d3y = f3.y - mean;
    float d4x = f4.x - mean, d4y = f4.y - mean, d5x = f5.x - mean, d5y = f5.y - mean;
    float q = d0x*d0x + d0y*d0y + d1x*d1x + d1y*d1y + d2x*d2x + d2y*d2y
            + d3x*d3x + d3y*d3y + d4x*d4x + d4y*d4y + d5x*d5x + d5y*d5y;
    #pragma unroll
    for (int o2 = 16; o2; o2 >>= 1) q += __shfl_xor_sync(0xFFFFFFFFu, q, o2);
    float inv = rsqrtf(q * (1.0f / 384.0f) + 1e-5f);

    float4 g0 = *(const float4*)(g + lane * 4);
    float4 g1 = *(const float4*)(g + lane * 4 + 128);
    float4 g2 = *(const float4*)(g + lane * 4 + 256);
    float4 b0 = *(const float4*)(b + lane * 4);
    float4 b1 = *(const float4*)(b + lane * 4 + 128);
    float4 b2v = *(const float4*)(b + lane * 4 + 256);

    __half2* op = (__half2*)(out + (size_t)row * DM);
    op[b2]       = __floats2half2_rn(d0x*inv*g0.x + b0.x,  d0y*inv*g0.y + b0.y);
    op[b2 + 1]   = __floats2half2_rn(d1x*inv*g0.z + b0.z,  d1y*inv*g0.w + b0.w);
    op[b2 + 64]  = __floats2half2_rn(d2x*inv*g1.x + b1.x,  d2y*inv*g1.y + b1.y);
    op[b2 + 65]  = __floats2half2_rn(d3x*inv*g1.z + b1.z,  d3y*inv*g1.w + b1.w);
    op[b2 + 128] = __floats2half2_rn(d4x*inv*g2.x + b2v.x, d4y*inv*g2.y + b2v.y);
    op[b2 + 129] = __floats2half2_rn(d5x*inv*g2.z + b2v.z, d5y*inv*g2.w + b2v.w);
}

// ---------------- mean-pool over L + classifier ----------------
__global__ __launch_bounds__(384) void cls_kernel(
    const __half* __restrict__ t, const float* __restrict__ w,
    const float* __restrict__ b, float* __restrict__ out)
{
    __shared__ float red[384];
    int n = blockIdx.x, d = threadIdx.x;
    float s = 0.f;
    for (int l = 0; l < 128; l++) s += __half2float(t[(size_t)(n * 128 + l) * DM + d]);
    red[d] = (s * (1.0f / 128.0f)) * w[d];
    __syncthreads();
    if (d < 128) red[d] += red[d + 128] + red[d + 256];
    __syncthreads();
    for (int st = 64; st > 0; st >>= 1) { if (d < st) red[d] += red[d + st]; __syncthreads(); }
    if (d == 0) out[n] = red[0] + b[0];
}

// ---------------- launcher ----------------
extern "C" void kernel_launch(void* const* d_in, const int* in_sizes, int n_in,
                              void* d_out, int out_size)
{
    const float* x   = (const float*)d_in[0];
    const float* cw0 = (const float*)d_in[1];
    const float* cb0 = (const float*)d_in[2];
    const float* cw1 = (const float*)d_in[3];
    const float* cb1 = (const float*)d_in[4];
    const float* cw2 = (const float*)d_in[5];
    const float* cb2 = (const float*)d_in[6];
    const float* ew  = (const float*)d_in[7];
    const float* eb  = (const float*)d_in[8];

    const float *Wq,*Wk,*Wv,*Wo,*W1,*W2,*bq,*bk,*bv,*bo,*b1,*b2;
    if (in_sizes[10] == 1536) {
        Wq=(const float*)d_in[9];  bq=(const float*)d_in[10];
        Wk=(const float*)d_in[11]; bk=(const float*)d_in[12];
        Wv=(const float*)d_in[13]; bv=(const float*)d_in[14];
        Wo=(const float*)d_in[15]; bo=(const float*)d_in[16];
        W1=(const float*)d_in[17]; b1=(const float*)d_in[18];
        W2=(const float*)d_in[19]; b2=(const float*)d_in[20];
    } else {
        Wq=(const float*)d_in[9];  Wk=(const float*)d_in[10];
        Wv=(const float*)d_in[11]; Wo=(const float*)d_in[12];
        W1=(const float*)d_in[13]; W2=(const float*)d_in[14];
        bq=(const float*)d_in[15]; bk=(const float*)d_in[16];
        bv=(const float*)d_in[17]; bo=(const float*)d_in[18];
        b1=(const float*)d_in[19]; b2=(const float*)d_in[20];
    }
    const float* g1  = (const float*)d_in[21];
    const float* be1 = (const float*)d_in[22];
    const float* g2  = (const float*)d_in[23];
    const float* be2 = (const float*)d_in[24];
    const float* clw = (const float*)d_in[25];
    const float* clb = (const float*)d_in[26];
    float* out = (float*)d_out;

    __half *p_feat,*p_t,*p_q,*p_k,*p_v,*p_ao,*p_buf,*p_mid;
    __half *p_bte,*p_btq,*p_btk,*p_btv,*p_bto,*p_bt1,*p_bt2;
    float *p_pe;
    cudaGetSymbolAddress((void**)&p_feat, h_feat);
    cudaGetSymbolAddress((void**)&p_t,   h_t);
    cudaGetSymbolAddress((void**)&p_q,   h_q);
    cudaGetSymbolAddress((void**)&p_k,   h_k);
    cudaGetSymbolAddress((void**)&p_v,   h_v);
    cudaGetSymbolAddress((void**)&p_ao,  h_ao);
    cudaGetSymbolAddress((void**)&p_buf, h_buf);
    cudaGetSymbolAddress((void**)&p_mid, h_mid);
    cudaGetSymbolAddress((void**)&p_pe,  d_pe);
    cudaGetSymbolAddress((void**)&p_bte, h_bte);
    cudaGetSymbolAddress((void**)&p_btq, h_btq);
    cudaGetSymbolAddress((void**)&p_btk, h_btk);
    cudaGetSymbolAddress((void**)&p_btv, h_btv);
    cudaGetSymbolAddress((void**)&p_bto, h_bto);
    cudaGetSymbolAddress((void**)&p_bt1, h_bt1);
    cudaGetSymbolAddress((void**)&p_bt2, h_bt2);

    cudaFuncSetAttribute(attn_kernel, cudaFuncAttributeMaxDynamicSharedMemorySize, ATTN_SMEM);

    dim3 tb(32, 8);
    pe_kernel<<<(LW*(DM/2) + 255)/256, 256>>>();
    cnn_kernel<<<NWIN, 256>>>(x, cw0, cb0, cw1, cb1, cw2, cb2);
    transpose_h<<<dim3(FEATD/32, DM/32, 1), tb>>>(ew, p_bte, FEATD, DM);
    transpose_h_qkvo<<<dim3(DM/32, DM/32, 16), tb>>>(Wq, Wk, Wv, Wo,
                                                     p_btq, p_btk, p_btv, p_bto);
    transpose_h<<<dim3(DM/32, DFF/32, 4), tb>>>(W1, p_bt1, DM, DFF);
    // embed: t = h( relu(feat @ ew + eb) + pe )
    gemm_h<<<dim3(DM/128, NWIN/64), 256, GSMEM>>>(p_feat, p_bte, eb, p_pe, p_t, FEATD, DM, 3);
    transpose_h<<<dim3(DFF/32, DM/32, 4), tb>>>(W2, p_bt2, DFF, DM);

    for (int i = 0; i < 4; i++) {
        gemm_h_qkv<<<dim3(9, NWIN/64), 256, GSMEM>>>(
            p_t,
            p_btq + (size_t)i*DM*DM, p_btk + (size_t)i*DM*DM, p_btv + (size_t)i*DM*DM,
            bq + i*DM, bk + i*DM, bv + i*DM,
            p_q, p_k, p_v);

        attn_kernel<<<dim3(NB, HH), 256, ATTN_SMEM>>>(p_q, p_k, p_v, p_ao);

        gemm_h<<<dim3(DM/128, NWIN/64), 256, GSMEM>>>(
            p_ao, p_bto + (size_t)i*DM*DM, bo + i*DM, p_t, p_buf, DM, DM, 2);
        ln_kernel<<<NWIN/8, 256>>>(p_buf, g1 + i*DM, be1 + i*DM, p_t);

        gemm_h<<<dim3(DFF/128, NWIN/64), 256, GSMEM>>>(
            p_t, p_bt1 + (size_t)i*DFF*DM, b1 + i*DFF, nullptr, p_mid, DM, DFF, 1);
        gemm_h<<<dim3(DM/128, NWIN/64), 256, GSMEM>>>(
            p_mid, p_bt2 + (size_t)i*DM*DFF, b2 + i*DM, p_t, p_buf, DFF, DM, 2);
        ln_kernel<<<NWIN/8, 256>>>(p_buf, g2 + i*DM, be2 + i*DM, p_t);
    }

    cls_kernel<<<NB, 384>>>(p_t, clw, clb, out);
}

// round 15
// speedup vs baseline: 1.9056x; 1.1922x over previous
#include <cuda_runtime.h>
#include <cuda_fp16.h>
#include <math.h>
#include <stdint.h>

// ---------------- problem constants ----------------
#define NB    64
#define LW    128
#define DM    384
#define HH    8
#define DFF   1536
#define NWIN  (NB*LW)     // 8192
#define FEATD 2048

// ---------------- scratch (device globals, alloc-free) ----------------
__device__ __half h_feat[NWIN*FEATD];
__device__ __half h_im  [(size_t)NWIN*64*128];   // im2col for CNN stage 2 (134 MB)
__device__ __half h_w2p [64*128];                // padded stage-2 weights
__device__ __half h_t  [NWIN*DM];
__device__ __half h_q  [NWIN*DM];
__device__ __half h_k  [NWIN*DM];
__device__ __half h_v  [NWIN*DM];
__device__ __half h_ao [NWIN*DM];
__device__ __half h_buf[NWIN*DM];
__device__ __half h_mid[NWIN*DFF];
__device__ float  d_pe [LW*DM];
__device__ __half h_bte[DM*FEATD];
__device__ __half h_btq[4][DM*DM];
__device__ __half h_btk[4][DM*DM];
__device__ __half h_btv[4][DM*DM];
__device__ __half h_bto[4][DM*DM];
__device__ __half h_bt1[4][DFF*DM];
__device__ __half h_bt2[4][DM*DFF];

// ---------------- helpers ----------------
__device__ __forceinline__ uint32_t smem_u32(const void* p) {
    uint32_t a;
    asm("{ .reg .u64 t; cvta.to.shared.u64 t, %1; cvt.u32.u64 %0, t; }" : "=r"(a) : "l"(p));
    return a;
}
__device__ __forceinline__ void cp16(uint32_t s, const void* g) {
    asm volatile("cp.async.cg.shared.global [%0], [%1], 16;" :: "r"(s), "l"(g));
}
__device__ __forceinline__ void cp_commit() { asm volatile("cp.async.commit_group;"); }
template<int N> __device__ __forceinline__ void cp_wait() {
    asm volatile("cp.async.wait_group %0;" :: "n"(N));
}
__device__ __forceinline__ void ldsm4(uint32_t* r, uint32_t addr) {
    asm volatile("ldmatrix.sync.aligned.m8n8.x4.shared.b16 {%0,%1,%2,%3}, [%4];"
        : "=r"(r[0]), "=r"(r[1]), "=r"(r[2]), "=r"(r[3]) : "r"(addr));
}
__device__ __forceinline__ void ldsm4t(uint32_t* r, uint32_t addr) {
    asm volatile("ldmatrix.sync.aligned.m8n8.x4.trans.shared.b16 {%0,%1,%2,%3}, [%4];"
        : "=r"(r[0]), "=r"(r[1]), "=r"(r[2]), "=r"(r[3]) : "r"(addr));
}
// m16n8k16 fp16 mma, fp32 accumulate
__device__ __forceinline__ void mma16(float* c, const uint32_t* a, uint32_t b0, uint32_t b1) {
    asm volatile("mma.sync.aligned.m16n8k16.row.col.f32.f16.f16.f32 "
        "{%0,%1,%2,%3}, {%4,%5,%6,%7}, {%8,%9}, {%0,%1,%2,%3};"
        : "+f"(c[0]), "+f"(c[1]), "+f"(c[2]), "+f"(c[3])
        : "r"(a[0]), "r"(a[1]), "r"(a[2]), "r"(a[3]), "r"(b0), "r"(b1));
}

// SMEM per stage: A [64][40] halfs + B [128][40] halfs (rows 32 -> pad 40 halfs = 80 B)
#define ROWB    80
#define ATILEB  (64*ROWB)       // 5120
#define BTILEB  (128*ROWB)      // 10240
#define STAGEB  (ATILEB+BTILEB) // 15360
#define GSMEM   (2*STAGEB)      // 30720 (2-stage, proven)

// ---------------- fp16 mma GEMM core: C tile 64x128, K chunks of 32, 2-stage ----------------
// epi: 0=+bias ; 1=relu(+bias) ; 2=+bias+extra_half[m*ldc+c] ; 3=relu(+bias)+pe_f32[(m&127)*ldc+c]
__device__ __forceinline__ void gemm_core(
    const __half* __restrict__ A, const __half* __restrict__ BtBlk,
    const float* __restrict__ bias, const void* __restrict__ extra,
    __half* __restrict__ C, int K, int ldc, int epi, int row0, int col0)
{
    extern __shared__ float sm[];
    uint32_t sbase = smem_u32(sm);
    int tid = threadIdx.x;

    int lrow = tid >> 2, lc = tid & 3;
    const __half* Ag  = A + (size_t)(row0 + lrow) * K + lc * 8;
    const __half* Bg0 = BtBlk + (size_t)lrow * K + lc * 8;
    const __half* Bg1 = BtBlk + (size_t)(lrow + 64) * K + lc * 8;
    uint32_t sA  = sbase + lrow * ROWB + lc * 16;
    uint32_t sB0 = sbase + ATILEB + lrow * ROWB + lc * 16;
    uint32_t sB1 = sB0 + 64 * ROWB;
    int nk = K >> 5;

    cp16(sA, Ag); cp16(sB0, Bg0); cp16(sB1, Bg1);
    cp_commit();

    int lane = tid & 31, w = tid >> 5, wm = w & 1, wn = w >> 1;
    uint32_t aoff = sbase + (wm * 32 + (lane & 15)) * ROWB + (lane >> 4) * 16;
    uint32_t boff = sbase + ATILEB + (wn * 32 + (lane & 15)) * ROWB + (lane >> 4) * 16;

    float c[2][4][4];
    #pragma unroll
    for (int i = 0; i < 2; i++)
        #pragma unroll
        for (int j = 0; j < 4; j++)
            #pragma unroll
            for (int q = 0; q < 4; q++) c[i][j][q] = 0.f;

    for (int kc = 0; kc < nk; kc++) {
        cp_wait<0>();
        __syncthreads();
        if (kc + 1 < nk) {
            uint32_t off = ((kc + 1) & 1) * STAGEB;
            int ho = (kc + 1) * 32;
            cp16(sA + off,  Ag + ho);
            cp16(sB0 + off, Bg0 + ho);
            cp16(sB1 + off, Bg1 + ho);
            cp_commit();
        }
        uint32_t st = (kc & 1) * STAGEB;
        uint32_t ab = aoff + st;
        uint32_t bb = boff + st;
        #pragma unroll
        for (int ks = 0; ks < 2; ks++) {
            uint32_t af[2][4], bf[2][4];
            #pragma unroll
            for (int mf = 0; mf < 2; mf++)
                ldsm4(af[mf], ab + mf * 16 * ROWB + ks * 32);
            #pragma unroll
            for (int np = 0; np < 2; np++)
                ldsm4(bf[np], bb + np * 16 * ROWB + ks * 32);
            #pragma unroll
            for (int mf = 0; mf < 2; mf++)
                #pragma unroll
                for (int nf = 0; nf < 4; nf++) {
                    int np = nf >> 1, sub = nf & 1;
                    mma16(c[mf][nf], af[mf], bf[np][sub], bf[np][sub + 2]);
                }
        }
    }

    #pragma unroll
    for (int mf = 0; mf < 2; mf++) {
        #pragma unroll
        for (int half = 0; half < 2; half++) {
            int r = row0 + wm * 32 + mf * 16 + (lane >> 2) + half * 8;
            #pragma unroll
            for (int nf = 0; nf < 4; nf++) {
                int col = col0 + wn * 32 + nf * 8 + (lane & 3) * 2;
                float v0 = c[mf][nf][half * 2 + 0] + bias[col];
                float v1 = c[mf][nf][half * 2 + 1] + bias[col + 1];
                if (epi == 1) { v0 = fmaxf(v0, 0.f); v1 = fmaxf(v1, 0.f); }
                else if (epi == 2) {
                    __half2 e = *(const __half2*)((const __half*)extra + (size_t)r * ldc + col);
                    v0 += __low2float(e); v1 += __high2float(e);
                } else if (epi == 3) {
                    const float* ex = (const float*)extra + (size_t)(r & (LW - 1)) * ldc;
                    v0 = fmaxf(v0, 0.f) + ex[col];
                    v1 = fmaxf(v1, 0.f) + ex[col + 1];
                }
                *(__half2*)(C + (size_t)r * ldc + col) = __floats2half2_rn(v0, v1);
            }
        }
    }
}

__global__ __launch_bounds__(256, 3) void gemm_h(
    const __half* __restrict__ A, const __half* __restrict__ Bt,
    const float* __restrict__ bias, const void* __restrict__ extra,
    __half* __restrict__ C, int K, int N, int epi)
{
    gemm_core(A, Bt + (size_t)blockIdx.x * 128 * K, bias, extra, C, K, N, epi,
              blockIdx.y * 64, blockIdx.x * 128);
}

__global__ __launch_bounds__(256, 3) void gemm_h_qkv(
    const __half* __restrict__ A,
    const __half* __restrict__ btq, const __half* __restrict__ btk, const __half* __restrict__ btv,
    const float* __restrict__ bqv, const float* __restrict__ bkv, const float* __restrict__ bvv,
    __half* __restrict__ q, __half* __restrict__ k, __half* __restrict__ v)
{
    int sel = blockIdx.x / 3, j = blockIdx.x % 3;
    const __half* Bt   = sel == 0 ? btq : (sel == 1 ? btk : btv);
    const float* bias  = sel == 0 ? bqv : (sel == 1 ? bkv : bvv);
    __half*      C     = sel == 0 ? q   : (sel == 1 ? k   : v);
    gemm_core(A, Bt + (size_t)j * 128 * DM, bias, nullptr, C, DM, DM, 0,
              blockIdx.y * 64, j * 128);
}

// ---------------- CNN stage-2 GEMM + fused maxpool/relu ----------------
// C tile 128(M=positions) x 64(N=channels), K=128; warps 4x2.
// Pool pairs rows (2p,2p+1) via shfl_xor(lane,4); stage via SMEM for coalesced feat stores.
__global__ __launch_bounds__(256, 3) void gemm_pool(
    const __half* __restrict__ A, const __half* __restrict__ Bt,
    const float* __restrict__ bias, __half* __restrict__ feat)
{
    extern __shared__ float sm[];
    uint32_t sbase = smem_u32(sm);
    int tid = threadIdx.x;
    int row0 = blockIdx.x * 128;

    int lrow = tid >> 2, lc = tid & 3;
    const __half* Ag0 = A + ((size_t)row0 + lrow) * 128 + lc * 8;
    const __half* Ag1 = Ag0 + (size_t)64 * 128;
    const __half* Bg  = Bt + (size_t)lrow * 128 + lc * 8;
    uint32_t sA0 = sbase + lrow * ROWB + lc * 16;
    uint32_t sA1 = sA0 + 64 * ROWB;
    uint32_t sB  = sbase + 10240 + lrow * ROWB + lc * 16;   // A tile 128*80=10240

    cp16(sA0, Ag0); cp16(sA1, Ag1); cp16(sB, Bg);
    cp_commit();

    int lane = tid & 31, w = tid >> 5, wm = w & 3, wn = w >> 2;
    uint32_t aoff = sbase + (wm * 32 + (lane & 15)) * ROWB + (lane >> 4) * 16;
    uint32_t boff = sbase + 10240 + (wn * 32 + (lane & 15)) * ROWB + (lane >> 4) * 16;

    float c[2][4][4];
    #pragma unroll
    for (int i = 0; i < 2; i++)
        #pragma unroll
        for (int j = 0; j < 4; j++)
            #pragma unroll
            for (int q = 0; q < 4; q++) c[i][j][q] = 0.f;

    #pragma unroll
    for (int kc = 0; kc < 4; kc++) {
        cp_wait<0>();
        __syncthreads();
        if (kc + 1 < 4) {
            uint32_t off = ((kc + 1) & 1) * STAGEB;
            int ho = (kc + 1) * 32;
            cp16(sA0 + off, Ag0 + ho);
            cp16(sA1 + off, Ag1 + ho);
            cp16(sB + off,  Bg + ho);
            cp_commit();
        }
        uint32_t st = (kc & 1) * STAGEB;
        uint32_t ab = aoff + st;
        uint32_t bb = boff + st;
        #pragma unroll
        for (int ks = 0; ks < 2; ks++) {
            uint32_t af[2][4], bf[2][4];
            #pragma unroll
            for (int mf = 0; mf < 2; mf++)
                ldsm4(af[mf], ab + mf * 16 * ROWB + ks * 32);
            #pragma unroll
            for (int np = 0; np < 2; np++)
                ldsm4(bf[np], bb + np * 16 * ROWB + ks * 32);
            #pragma unroll
            for (int mf = 0; mf < 2; mf++)
                #pragma unroll
                for (int nf = 0; nf < 4; nf++) {
                    int np = nf >> 1, sub = nf & 1;
                    mma16(c[mf][nf], af[mf], bf[np][sub], bf[np][sub + 2]);
                }
        }
    }

    // pooled outputs -> SMEM (2 windows x 64ch x 32pos = 4096 halfs)
    __syncthreads();
    __half* sfeat = (__half*)sm;
    #pragma unroll
    for (int mf = 0; mf < 2; mf++) {
        #pragma unroll
        for (int half = 0; half < 2; half++) {
            int rl = wm * 32 + mf * 16 + (lane >> 2) + half * 8;
            #pragma unroll
            for (int nf = 0; nf < 4; nf++) {
                int col = wn * 32 + nf * 8 + (lane & 3) * 2;
                float v0 = c[mf][nf][half * 2 + 0] + bias[col];
                float v1 = c[mf][nf][half * 2 + 1] + bias[col + 1];
                float p0 = __shfl_xor_sync(0xFFFFFFFFu, v0, 4);
                float p1 = __shfl_xor_sync(0xFFFFFFFFu, v1, 4);
                if (((lane >> 2) & 1) == 0) {
                    int wl = rl >> 6, pp = (rl & 63) >> 1;
                    sfeat[wl * 2048 + col * 32 + pp]       = __float2half_rn(fmaxf(fmaxf(v0, p0), 0.f));
                    sfeat[wl * 2048 + (col + 1) * 32 + pp] = __float2half_rn(fmaxf(fmaxf(v1, p1), 0.f));
                }
            }
        }
    }
    __syncthreads();
    float4* dstf = (float4*)(feat + (size_t)(row0 >> 6) * 2048);
    const float4* srcf = (const float4*)sfeat;
    for (int i = tid; i < 512; i += 256)
        dstf[i] = srcf[i];
}

// pad stage-2 weights: h_w2p[c][j] = w2[c*112+j] for j<112, else 0
__global__ void w2pad_kernel(const float* __restrict__ w2)
{
    int i = blockIdx.x * 256 + threadIdx.x;
    if (i >= 64 * 128) return;
    int c = i >> 7, col = i & 127;
    h_w2p[i] = __float2half_rn(col < 112 ? w2[c * 112 + col] : 0.f);
}

// ---------------- batched weight transpose -> fp16 ----------------
__global__ void transpose_h(const float* __restrict__ in, __half* __restrict__ out, int Kd, int Nd)
{
    size_t mstride = (size_t)Kd * Nd;
    in  += blockIdx.z * mstride;
    out += blockIdx.z * mstride;
    __shared__ float tile[32][33];
    int kb = blockIdx.x * 32, nb = blockIdx.y * 32;
    int tx = threadIdx.x, ty = threadIdx.y;
    #pragma unroll
    for (int j = 0; j < 32; j += 8)
        tile[ty + j][tx] = in[(size_t)(kb + ty + j) * Nd + nb + tx];
    __syncthreads();
    #pragma unroll
    for (int j = 0; j < 32; j += 8)
        out[(size_t)(nb + ty + j) * Kd + kb + tx] = __float2half_rn(tile[tx][ty + j]);
}

__global__ void transpose_h_qkvo(
    const float* __restrict__ Wq, const float* __restrict__ Wk,
    const float* __restrict__ Wv, const float* __restrict__ Wo,
    __half* __restrict__ oq, __half* __restrict__ ok,
    __half* __restrict__ ov, __half* __restrict__ oo)
{
    int z = blockIdx.z, sel = z >> 2, layer = z & 3;
    const float* in = (sel == 0 ? Wq : sel == 1 ? Wk : sel == 2 ? Wv : Wo)
                      + (size_t)layer * DM * DM;
    __half* out = (sel == 0 ? oq : sel == 1 ? ok : sel == 2 ? ov : oo)
                  + (size_t)layer * DM * DM;
    __shared__ float tile[32][33];
    int kb = blockIdx.x * 32, nb = blockIdx.y * 32;
    int tx = threadIdx.x, ty = threadIdx.y;
    #pragma unroll
    for (int j = 0; j < 32; j += 8)
        tile[ty + j][tx] = in[(size_t)(kb + ty + j) * DM + nb + tx];
    __syncthreads();
    #pragma unroll
    for (int j = 0; j < 32; j += 8)
        out[(size_t)(nb + ty + j) * DM + kb + tx] = __float2half_rn(tile[tx][ty + j]);
}

// ---------------- positional encoding ----------------
__global__ void pe_kernel() {
    int idx = blockIdx.x * blockDim.x + threadIdx.x;
    if (idx >= LW * (DM / 2)) return;
    int l = idx / (DM / 2);
    int i = idx % (DM / 2);
    double ang = (double)l / pow(10000.0, (2.0 * i) / (double)DM);
    d_pe[l * DM + 2 * i]     = (float)sin(ang);
    d_pe[l * DM + 2 * i + 1] = (float)cos(ang);
}

// ---------------- CNN stages 0+1 + im2col emit: one block per window ----------------
__global__ __launch_bounds__(256) void cnn01_kernel(
    const float* __restrict__ x,
    const float* __restrict__ w0, const float* __restrict__ b0,
    const float* __restrict__ w1, const float* __restrict__ b1)
{
    __shared__ float sx[256];
    __shared__ float a0[4 * 128];
    __shared__ float a1[16 * 64];
    __shared__ float sw0[28];
    __shared__ float sw1[448];
    __shared__ float sb0[4], sb1[16];

    int win = blockIdx.x;
    int tid = threadIdx.x;

    sx[tid] = x[win * 256 + tid];
    if (tid < 28) sw0[tid] = w0[tid];
    if (tid < 4)  sb0[tid] = b0[tid];
    for (int i = tid; i < 448; i += 256) sw1[i] = w1[i];
    if (tid < 16) sb1[tid] = b1[tid];
    __syncthreads();

    // stage 0: conv(1->4,k7,p3)+relu+pool2 : 256 -> 4x128
    for (int it = tid; it < 4 * 128; it += 256) {
        int c = it >> 7, p = it & 127;
        float acc0 = sb0[c], acc1 = sb0[c];
        #pragma unroll
        for (int k = 0; k < 7; k++) {
            float wv = sw0[c * 7 + k];
            int i0 = 2 * p + k - 3, i1 = i0 + 1;
            if (i0 >= 0 && i0 < 256) acc0 += sx[i0] * wv;
            if (i1 >= 0 && i1 < 256) acc1 += sx[i1] * wv;
        }
        a0[c * 128 + p] = fmaxf(fmaxf(acc0, acc1), 0.f);
    }
    __syncthreads();

    // stage 1: conv(4->16)+relu+pool : 4x128 -> 16x64
    for (int it = tid; it < 16 * 64; it += 256) {
        int c = it >> 6, p = it & 63;
        float acc0 = sb1[c], acc1 = sb1[c];
        for (int ci = 0; ci < 4; ci++) {
            const float* wrow = &sw1[(c * 4 + ci) * 7];
            const float* arow = &a0[ci * 128];
            #pragma unroll
            for (int k = 0; k < 7; k++) {
                float wv = wrow[k];
                int i0 = 2 * p + k - 3, i1 = i0 + 1;
                if (i0 >= 0 && i0 < 128) acc0 += arow[i0] * wv;
                if (i1 >= 0 && i1 < 128) acc1 += arow[i1] * wv;
            }
        }
        a1[c * 64 + p] = fmaxf(fmaxf(acc0, acc1), 0.f);
    }
    __syncthreads();

    // im2col emit: row p (0..63, pre-pool position), col = ci*7+k (pad 112->128)
    {
        int p = tid >> 2;          // 0..63
        int seg = tid & 3;         // cols seg*32..+31
        __half vals[32];
        #pragma unroll
        for (int j = 0; j < 32; j++) {
            int col = seg * 32 + j;
            float v = 0.f;
            if (col < 112) {
                int ci = col / 7, kk = col - ci * 7;
                int idx = p + kk - 3;
                if (idx >= 0 && idx < 64) v = a1[ci * 64 + idx];
            }
            vals[j] = __float2half_rn(v);
        }
        float4* dst = (float4*)(h_im + ((size_t)win * 64 + p) * 128 + seg * 32);
        const float4* src = (const float4*)vals;
        dst[0] = src[0]; dst[1] = src[1]; dst[2] = src[2]; dst[3] = src[3];
    }
}

// ---------------- tensor-core attention: one block per (n,h), 8 warps ----------------
#define AROW  112
#define PROW  272
#define ASM_Q 0
#define ASM_K 14336
#define ASM_V 28672
#define ASM_P 43008
#define ATTN_SMEM (43008 + 128*PROW)   // 77824

__global__ __launch_bounds__(256) void attn_kernel(
    const __half* __restrict__ q, const __half* __restrict__ k,
    const __half* __restrict__ v, __half* __restrict__ o)
{
    extern __shared__ char asmem[];
    uint32_t sb = smem_u32(asmem);
    int n = blockIdx.x, h = blockIdx.y;
    int tid = threadIdx.x, lane = tid & 31, wid = tid >> 5;

    for (int f = tid; f < 768; f += 256) {
        int s = f / 6, j = f % 6;
        size_t g = (size_t)(n * 128 + s) * DM + h * 48 + j * 8;
        cp16(sb + ASM_Q + s * AROW + j * 16, q + g);
        cp16(sb + ASM_K + s * AROW + j * 16, k + g);
        cp16(sb + ASM_V + s * AROW + j * 16, v + g);
    }
    cp_commit();
    cp_wait<0>();
    __syncthreads();

    float c[16][4];
    #pragma unroll
    for (int i = 0; i < 16; i++)
        #pragma unroll
        for (int j = 0; j < 4; j++) c[i][j] = 0.f;

    uint32_t qaddr = sb + ASM_Q + (wid * 16 + (lane & 15)) * AROW + (lane >> 4) * 16;
    #pragma unroll
    for (int ks = 0; ks < 3; ks++) {
        uint32_t af[4];
        ldsm4(af, qaddr + ks * 32);
        #pragma unroll
        for (int nt2 = 0; nt2 < 8; nt2++) {
            uint32_t bf[4];
            ldsm4(bf, sb + ASM_K + (nt2 * 16 + (lane & 15)) * AROW + (lane >> 4) * 16 + ks * 32);
            mma16(c[nt2 * 2],     af, bf[0], bf[2]);
            mma16(c[nt2 * 2 + 1], af, bf[1], bf[3]);
        }
    }

    const float temp = 0.14433756729740643f;
    float mx0 = -1e30f, mx1 = -1e30f;
    #pragma unroll
    for (int nt = 0; nt < 16; nt++) {
        c[nt][0] *= temp; c[nt][1] *= temp; c[nt][2] *= temp; c[nt][3] *= temp;
        mx0 = fmaxf(mx0, fmaxf(c[nt][0], c[nt][1]));
        mx1 = fmaxf(mx1, fmaxf(c[nt][2], c[nt][3]));
    }
    #pragma unroll
    for (int d2 = 1; d2 <= 2; d2 <<= 1) {
        mx0 = fmaxf(mx0, __shfl_xor_sync(0xFFFFFFFFu, mx0, d2));
        mx1 = fmaxf(mx1, __shfl_xor_sync(0xFFFFFFFFu, mx1, d2));
    }
    float s0 = 0.f, s1 = 0.f;
    int prow0 = wid * 16 + (lane >> 2);
    int pcol  = (lane & 3) * 2;
    #pragma unroll
    for (int nt = 0; nt < 16; nt++) {
        float p0 = __expf(c[nt][0] - mx0);
        float p1 = __expf(c[nt][1] - mx0);
        float p2 = __expf(c[nt][2] - mx1);
        float p3 = __expf(c[nt][3] - mx1);
        s0 += p0 + p1; s1 += p2 + p3;
        *(__half2*)(asmem + ASM_P + prow0 * PROW + (nt * 8 + pcol) * 2)       = __floats2half2_rn(p0, p1);
        *(__half2*)(asmem + ASM_P + (prow0 + 8) * PROW + (nt * 8 + pcol) * 2) = __floats2half2_rn(p2, p3);
    }
    #pragma unroll
    for (int d2 = 1; d2 <= 2; d2 <<= 1) {
        s0 += __shfl_xor_sync(0xFFFFFFFFu, s0, d2);
        s1 += __shfl_xor_sync(0xFFFFFFFFu, s1, d2);
    }
    float inv0 = 1.0f / s0, inv1 = 1.0f / s1;
    __syncwarp();

    float oacc[6][4];
    #pragma unroll
    for (int i = 0; i < 6; i++)
        #pragma unroll
        for (int j = 0; j < 4; j++) oacc[i][j] = 0.f;

    uint32_t paddr = sb + ASM_P + (wid * 16 + (lane & 15)) * PROW + (lane >> 4) * 16;
    #pragma unroll
    for (int ks = 0; ks < 8; ks++) {
        uint32_t af[4];
        ldsm4(af, paddr + ks * 32);
        #pragma unroll
        for (int nb = 0; nb < 3; nb++) {
            uint32_t bf[4];
            ldsm4t(bf, sb + ASM_V + (ks * 16 + (lane & 15)) * AROW + nb * 32 + (lane >> 4) * 16);
            mma16(oacc[nb * 2],     af, bf[0], bf[1]);
            mma16(oacc[nb * 2 + 1], af, bf[2], bf[3]);
        }
    }

    __half* op0 = o + (size_t)(n * 128 + prow0) * DM + h * 48 + pcol;
    __half* op1 = op0 + (size_t)8 * DM;
    #pragma unroll
    for (int nt = 0; nt < 6; nt++) {
        *(__half2*)(op0 + nt * 8) = __floats2half2_rn(oacc[nt][0] * inv0, oacc[nt][1] * inv0);
        *(__half2*)(op1 + nt * 8) = __floats2half2_rn(oacc[nt][2] * inv1, oacc[nt][3] * inv1);
    }
}

// ---------------- layernorm (384): warp per row, 8 rows per block; half in/out ----------------
__global__ __launch_bounds__(256) void ln_kernel(
    const __half* __restrict__ in, const float* __restrict__ g,
    const float* __restrict__ b, __half* __restrict__ out)
{
    int row = blockIdx.x * 8 + (threadIdx.x >> 5);
    int lane = threadIdx.x & 31;
    const __half2* rp = (const __half2*)(in + (size_t)row * DM);
    int b2 = lane * 2;

    float2 f0 = __half22float2(rp[b2]),       f1 = __half22float2(rp[b2 + 1]);
    float2 f2 = __half22float2(rp[b2 + 64]),  f3 = __half22float2(rp[b2 + 65]);
    float2 f4 = __half22float2(rp[b2 + 128]), f5 = __half22float2(rp[b2 + 129]);

    float s = f0.x + f0.y + f1.x + f1.y + f2.x + f2.y + f3.x + f3.y + f4.x + f4.y + f5.x + f5.y;
    #pragma unroll
    for (int o2 = 16; o2; o2 >>= 1) s += __shfl_xor_sync(0xFFFFFFFFu, s, o2);
    float mean = s * (1.0f / 384.0f);

    float d0x = f0.x - mean, d0y = f0.y - mean, d1x = f1.x - mean, d1y = f1.y - mean;
    float d2x = f2.x - mean, d2y = f2.y - mean, d3x = f3.x - mean, d3y = f3.y - mean;
    float d4x = f4.x - mean, d4y = f4.y - mean, d5x = f5.x - mean, d5y = f5.y - mean;
    float q = d0x*d0x + d0y*d0y + d1x*d1x + d1y*d1y + d2x*d2x + d2y*d2y
            + d3x*d3x + d3y*d3y + d4x*d4x + d4y*d4y + d5x*d5x + d5y*d5y;
    #pragma unroll
    for (int o2 = 16; o2; o2 >>= 1) q += __shfl_xor_sync(0xFFFFFFFFu, q, o2);
    float inv = rsqrtf(q * (1.0f / 384.0f) + 1e-5f);

    float4 g0 = *(const float4*)(g + lane * 4);
    float4 g1 = *(const float4*)(g + lane * 4 + 128);
    float4 g2 = *(const float4*)(g + lane * 4 + 256);
    float4 b0 = *(const float4*)(b + lane * 4);
    float4 b1 = *(const float4*)(b + lane * 4 + 128);
    float4 b2v = *(const float4*)(b + lane * 4 + 256);

    __half2* op = (__half2*)(out + (size_t)row * DM);
    op[b2]       = __floats2half2_rn(d0x*inv*g0.x + b0.x,  d0y*inv*g0.y + b0.y);
    op[b2 + 1]   = __floats2half2_rn(d1x*inv*g0.z + b0.z,  d1y*inv*g0.w + b0.w);
    op[b2 + 64]  = __floats2half2_rn(d2x*inv*g1.x + b1.x,  d2y*inv*g1.y + b1.y);
    op[b2 + 65]  = __floats2half2_rn(d3x*inv*g1.z + b1.z,  d3y*inv*g1.w + b1.w);
    op[b2 + 128] = __floats2half2_rn(d4x*inv*g2.x + b2v.x, d4y*inv*g2.y + b2v.y);
    op[b2 + 129] = __floats2half2_rn(d5x*inv*g2.z + b2v.z, d5y*inv*g2.w + b2v.w);
}

// ---------------- mean-pool over L + classifier ----------------
__global__ __launch_bounds__(384) void cls_kernel(
    const __half* __restrict__ t, const float* __restrict__ w,
    const float* __restrict__ b, float* __restrict__ out)
{
    __shared__ float red[384];
    int n = blockIdx.x, d = threadIdx.x;
    float s = 0.f;
    for (int l = 0; l < 128; l++) s += __half2float(t[(size_t)(n * 128 + l) * DM + d]);
    red[d] = (s * (1.0f / 128.0f)) * w[d];
    __syncthreads();
    if (d < 128) red[d] += red[d + 128] + red[d + 256];
    __syncthreads();
    for (int st = 64; st > 0; st >>= 1) { if (d < st) red[d] += red[d + st]; __syncthreads(); }
    if (d == 0) out[n] = red[0] + b[0];
}

// ---------------- launcher ----------------
extern "C" void kernel_launch(void* const* d_in, const int* in_sizes, int n_in,
                              void* d_out, int out_size)
{
    const float* x   = (const float*)d_in[0];
    const float* cw0 = (const float*)d_in[1];
    const float* cb0 = (const float*)d_in[2];
    const float* cw1 = (const float*)d_in[3];
    const float* cb1 = (const float*)d_in[4];
    const float* cw2 = (const float*)d_in[5];
    const float* cb2 = (const float*)d_in[6];
    const float* ew  = (const float*)d_in[7];
    const float* eb  = (const float*)d_in[8];

    const float *Wq,*Wk,*Wv,*Wo,*W1,*W2,*bq,*bk,*bv,*bo,*b1,*b2;
    if (in_sizes[10] == 1536) {
        Wq=(const float*)d_in[9];  bq=(const float*)d_in[10];
        Wk=(const float*)d_in[11]; bk=(const float*)d_in[12];
        Wv=(const float*)d_in[13]; bv=(const float*)d_in[14];
        Wo=(const float*)d_in[15]; bo=(const float*)d_in[16];
        W1=(const float*)d_in[17]; b1=(const float*)d_in[18];
        W2=(const float*)d_in[19]; b2=(const float*)d_in[20];
    } else {
        Wq=(const float*)d_in[9];  Wk=(const float*)d_in[10];
        Wv=(const float*)d_in[11]; Wo=(const float*)d_in[12];
        W1=(const float*)d_in[13]; W2=(const float*)d_in[14];
        bq=(const float*)d_in[15]; bk=(const float*)d_in[16];
        bv=(const float*)d_in[17]; bo=(const float*)d_in[18];
        b1=(const float*)d_in[19]; b2=(const float*)d_in[20];
    }
    const float* g1  = (const float*)d_in[21];
    const float* be1 = (const float*)d_in[22];
    const float* g2  = (const float*)d_in[23];
    const float* be2 = (const float*)d_in[24];
    const float* clw = (const float*)d_in[25];
    const float* clb = (const float*)d_in[26];
    float* out = (float*)d_out;

    __half *p_feat,*p_im,*p_w2p,*p_t,*p_q,*p_k,*p_v,*p_ao,*p_buf,*p_mid;
    __half *p_bte,*p_btq,*p_btk,*p_btv,*p_bto,*p_bt1,*p_bt2;
    float *p_pe;
    cudaGetSymbolAddress((void**)&p_feat, h_feat);
    cudaGetSymbolAddress((void**)&p_im,  h_im);
    cudaGetSymbolAddress((void**)&p_w2p, h_w2p);
    cudaGetSymbolAddress((void**)&p_t,   h_t);
    cudaGetSymbolAddress((void**)&p_q,   h_q);
    cudaGetSymbolAddress((void**)&p_k,   h_k);
    cudaGetSymbolAddress((void**)&p_v,   h_v);
    cudaGetSymbolAddress((void**)&p_ao,  h_ao);
    cudaGetSymbolAddress((void**)&p_buf, h_buf);
    cudaGetSymbolAddress((void**)&p_mid, h_mid);
    cudaGetSymbolAddress((void**)&p_pe,  d_pe);
    cudaGetSymbolAddress((void**)&p_bte, h_bte);
    cudaGetSymbolAddress((void**)&p_btq, h_btq);
    cudaGetSymbolAddress((void**)&p_btk, h_btk);
    cudaGetSymbolAddress((void**)&p_btv, h_btv);
    cudaGetSymbolAddress((void**)&p_bto, h_bto);
    cudaGetSymbolAddress((void**)&p_bt1, h_bt1);
    cudaGetSymbolAddress((void**)&p_bt2, h_bt2);

    cudaFuncSetAttribute(attn_kernel, cudaFuncAttributeMaxDynamicSharedMemorySize, ATTN_SMEM);

    dim3 tb(32, 8);
    pe_kernel<<<(LW*(DM/2) + 255)/256, 256>>>();
    cnn01_kernel<<<NWIN, 256>>>(x, cw0, cb0, cw1, cb1);
    w2pad_kernel<<<(64*128 + 255)/256, 256>>>(cw2);
    transpose_h<<<dim3(FEATD/32, DM/32, 1), tb>>>(ew, p_bte, FEATD, DM);
    transpose_h_qkvo<<<dim3(DM/32, DM/32, 16), tb>>>(Wq, Wk, Wv, Wo,
                                                     p_btq, p_btk, p_btv, p_bto);
    // CNN stage 2 as GEMM + fused pool/relu
    gemm_pool<<<NWIN*64/128, 256, GSMEM>>>(p_im, p_w2p, cb2, p_feat);
    transpose_h<<<dim3(DM/32, DFF/32, 4), tb>>>(W1, p_bt1, DM, DFF);
    transpose_h<<<dim3(DFF/32, DM/32, 4), tb>>>(W2, p_bt2, DFF, DM);

    // embed: t = h( relu(feat @ ew + eb) + pe )
    gemm_h<<<dim3(DM/128, NWIN/64), 256, GSMEM>>>(p_feat, p_bte, eb, p_pe, p_t, FEATD, DM, 3);

    for (int i = 0; i < 4; i++) {
        gemm_h_qkv<<<dim3(9, NWIN/64), 256, GSMEM>>>(
            p_t,
            p_btq + (size_t)i*DM*DM, p_btk + (size_t)i*DM*DM, p_btv + (size_t)i*DM*DM,
            bq + i*DM, bk + i*DM, bv + i*DM,
            p_q, p_k, p_v);

        attn_kernel<<<dim3(NB, HH), 256, ATTN_SMEM>>>(p_q, p_k, p_v, p_ao);

        gemm_h<<<dim3(DM/128, NWIN/64), 256, GSMEM>>>(
            p_ao, p_bto + (size_t)i*DM*DM, bo + i*DM, p_t, p_buf, DM, DM, 2);
        ln_kernel<<<NWIN/8, 256>>>(p_buf, g1 + i*DM, be1 + i*DM, p_t);

        gemm_h<<<dim3(DFF/128, NWIN/64), 256, GSMEM>>>(
            p_t, p_bt1 + (size_t)i*DFF*DM, b1 + i*DFF, nullptr, p_mid, DM, DFF, 1);
        gemm_h<<<dim3(DM/128, NWIN/64), 256, GSMEM>>>(
            p_mid, p_bt2 + (size_t)i*DM*DFF, b2 + i*DM, p_t, p_buf, DFF, DM, 2);
        ln_kernel<<<NWIN/8, 256>>>(p_buf, g2 + i*DM, be2 + i*DM, p_t);
    }

    cls_kernel<<<NB, 384>>>(p_t, clw, clb, out);
}